// round 9
// baseline (speedup 1.0000x reference)
#include <cuda_runtime.h>
#include <cuda_bf16.h>
#include <cstdint>

#define BATCH 64
#define TLEN 2048
#define JLEN 128
#define DDIM 512

#define TT   128              // t per CTA (N tile)
#define KC   64               // k per chunk (64 bf16 = 128B row, SW128 atom)

// smem offsets (bytes) within 64KB dynamic smem
#define A_HI 0
#define A_LO 16384
#define B_HI 32768
#define B_LO 49152
#define SM_TOTAL 65536

#define SWZ128(off) ((off) ^ (((off) >> 3) & 0x70))

// Scratch
__device__ float g_sim[(size_t)BATCH * JLEN * TLEN];
__device__ float g_max[BATCH * JLEN];
__device__ float g_invden[BATCH * JLEN];
__device__ __nv_bfloat16 g_qhi[(size_t)BATCH * JLEN * DDIM];  // (question*w) hi
__device__ __nv_bfloat16 g_qlo[(size_t)BATCH * JLEN * DDIM];  // (question*w) lo

// ---------------------------------------------------------------------------
// helpers
// ---------------------------------------------------------------------------
__device__ __forceinline__ uint32_t smem_u32(const void* p) {
    uint32_t a;
    asm("{ .reg .u64 t; cvta.to.shared.u64 t, %1; cvt.u32.u64 %0, t; }" : "=r"(a) : "l"(p));
    return a;
}

#define LDSM_X4(R, ADDR) \
    asm volatile("ldmatrix.sync.aligned.m8n8.x4.shared.b16 {%0,%1,%2,%3}, [%4];" \
        : "=r"((R)[0]), "=r"((R)[1]), "=r"((R)[2]), "=r"((R)[3]) : "r"(ADDR))

#define CP_ASYNC16(dst, src) \
    asm volatile("cp.async.cg.shared.global [%0], [%1], 16;" :: "r"(dst), "l"(src))
#define CP_COMMIT() asm volatile("cp.async.commit_group;" ::: "memory")
#define CP_WAIT0()  asm volatile("cp.async.wait_group 0;" ::: "memory")

__device__ __forceinline__ void mma16816(float* d, const uint32_t* a, const uint32_t* b) {
    asm volatile(
        "mma.sync.aligned.m16n8k16.row.col.f32.bf16.bf16.f32 "
        "{%0,%1,%2,%3}, {%4,%5,%6,%7}, {%8,%9}, {%0,%1,%2,%3};"
        : "+f"(d[0]), "+f"(d[1]), "+f"(d[2]), "+f"(d[3])
        : "r"(a[0]), "r"(a[1]), "r"(a[2]), "r"(a[3]), "r"(b[0]), "r"(b[1]));
}

__device__ __forceinline__ uint32_t pack2bf(float a, float b) {
    __nv_bfloat16 ha = __float2bfloat16(a);
    __nv_bfloat16 hb = __float2bfloat16(b);
    return (uint32_t)__bfloat16_as_ushort(ha) | ((uint32_t)__bfloat16_as_ushort(hb) << 16);
}

// split float4 -> packed bf16 hi pair (h01,h23) and lo pair (l01,l23)
__device__ __forceinline__ void split4(const float4 v, uint32_t& h01, uint32_t& h23,
                                       uint32_t& l01, uint32_t& l23) {
    __nv_bfloat16 h0 = __float2bfloat16(v.x);
    __nv_bfloat16 h1 = __float2bfloat16(v.y);
    __nv_bfloat16 h2 = __float2bfloat16(v.z);
    __nv_bfloat16 h3 = __float2bfloat16(v.w);
    float r0 = v.x - __bfloat162float(h0);
    float r1 = v.y - __bfloat162float(h1);
    float r2 = v.z - __bfloat162float(h2);
    float r3 = v.w - __bfloat162float(h3);
    h01 = (uint32_t)__bfloat16_as_ushort(h0) | ((uint32_t)__bfloat16_as_ushort(h1) << 16);
    h23 = (uint32_t)__bfloat16_as_ushort(h2) | ((uint32_t)__bfloat16_as_ushort(h3) << 16);
    l01 = pack2bf(r0, r1);
    l23 = pack2bf(r2, r3);
}

// ---------------------------------------------------------------------------
// Kernel 0: split (question * w) into bf16 hi/lo global scratch
// ---------------------------------------------------------------------------
__global__ __launch_bounds__(128) void prep_kernel(
    const float* __restrict__ question,
    const float* __restrict__ weight)
{
    const int row = blockIdx.x;            // b*128 + j
    const int k4  = threadIdx.x * 4;
    const float4 q = __ldg(reinterpret_cast<const float4*>(question + (size_t)row * DDIM + k4));
    const float4 w = __ldg(reinterpret_cast<const float4*>(weight + k4));
    float4 v = make_float4(q.x * w.x, q.y * w.y, q.z * w.z, q.w * w.w);
    uint32_t h01, h23, l01, l23;
    split4(v, h01, h23, l01, l23);
    *reinterpret_cast<uint2*>(g_qhi + (size_t)row * DDIM + k4) = make_uint2(h01, h23);
    *reinterpret_cast<uint2*>(g_qlo + (size_t)row * DDIM + k4) = make_uint2(l01, l23);
}

// ---------------------------------------------------------------------------
// Kernel 1: HMMA GEMM. CTA = (t-tile of 128, b). Output D[j<ql(128)][t=128].
// 3-pass bf16 split, fp32 accum. 8 warps = 2(j) x 4(t); warp: 4 m16 x 4 n8.
// A staged via cp.async (already bf16); B converted in-kernel.
// ---------------------------------------------------------------------------
__global__ __launch_bounds__(256) void gemm_kernel(
    const float* __restrict__ context,
    const int* __restrict__ qlen,
    const int* __restrict__ clen)
{
    extern __shared__ __align__(1024) char smem[];
    const int b  = blockIdx.y;
    const int t0 = blockIdx.x * TT;
    if (t0 >= clen[b]) return;
    const int ql = qlen[b];
    const int qlr = (ql + 15) & ~15;    // rounded to m16 tiles

    const uint32_t sb = smem_u32(smem);
    const int tid  = threadIdx.x;
    const int lane = tid & 31;
    const int wid  = tid >> 5;

    const int jbase = (wid & 1) << 6;   // 0 or 64
    const int tbase = (wid >> 1) << 5;  // 0,32,64,96

    const int r    = lane & 7;
    const int quad = lane >> 3;

    float acc[4][4][4];
    #pragma unroll
    for (int mt = 0; mt < 4; ++mt)
        #pragma unroll
        for (int nt = 0; nt < 4; ++nt)
            #pragma unroll
            for (int i = 0; i < 4; ++i) acc[mt][nt][i] = 0.0f;

    for (int kb = 0; kb < DDIM; kb += KC) {
        // ---- stage A via cp.async (bf16 hi/lo) : rows < qlr ----
        #pragma unroll
        for (int it = 0; it < 4; ++it) {
            const int idx = tid + it * 256;       // 0..1023
            const int row = idx >> 3;
            const int u   = idx & 7;              // 16B unit within row
            if (row < qlr) {
                const size_t src = ((size_t)(b * JLEN + row)) * DDIM + kb + u * 8;
                const uint32_t off = SWZ128((uint32_t)(row * 128 + u * 16));
                CP_ASYNC16(sb + A_HI + off, g_qhi + src);
                CP_ASYNC16(sb + A_LO + off, g_qlo + src);
            }
        }
        CP_COMMIT();

        // ---- stage B (context fp32 -> bf16 split) : 128 rows x 64 k ----
        #pragma unroll
        for (int it = 0; it < 8; ++it) {
            const int idx = tid + it * 256;       // 0..2047
            const int row = idx >> 4;
            const int u   = idx & 15;             // float4 unit within row
            const float4 c = __ldg(reinterpret_cast<const float4*>(
                context + ((size_t)(b * TLEN + t0 + row)) * DDIM + kb + u * 4));
            uint32_t h01, h23, l01, l23;
            split4(c, h01, h23, l01, l23);
            const uint32_t off = SWZ128((uint32_t)(row * 128 + u * 8));
            *reinterpret_cast<uint2*>(smem + B_HI + off) = make_uint2(h01, h23);
            *reinterpret_cast<uint2*>(smem + B_LO + off) = make_uint2(l01, l23);
        }
        CP_WAIT0();
        __syncthreads();

        // ---- compute: 4 k16-steps ----
        #pragma unroll
        for (int ks = 0; ks < 4; ++ks) {
            uint32_t bh[8], bl[8];
            #pragma unroll
            for (int p = 0; p < 2; ++p) {
                const int tile  = p * 2 + (quad >> 1);
                const int khalf = quad & 1;
                const int rowt  = tbase + tile * 8 + r;
                const uint32_t off = SWZ128((uint32_t)(rowt * 128 + ks * 32 + khalf * 16));
                LDSM_X4(bh + p * 4, sb + B_HI + off);
                LDSM_X4(bl + p * 4, sb + B_LO + off);
            }
            #pragma unroll
            for (int mt = 0; mt < 4; ++mt) {
                if (jbase + mt * 16 < ql) {
                    const int rowa = jbase + mt * 16 + ((quad & 1) << 3) + r;
                    const uint32_t off = SWZ128((uint32_t)(rowa * 128 + ks * 32 + ((quad >> 1) << 4)));
                    uint32_t ah[4], al[4];
                    LDSM_X4(ah, sb + A_HI + off);
                    LDSM_X4(al, sb + A_LO + off);
                    #pragma unroll
                    for (int nt = 0; nt < 4; ++nt) {
                        mma16816(acc[mt][nt], ah, bh + nt * 2);
                        mma16816(acc[mt][nt], al, bh + nt * 2);
                        mma16816(acc[mt][nt], ah, bl + nt * 2);
                    }
                }
            }
        }
        __syncthreads();
    }

    // ---- epilogue: D[j][t] -> g_sim[b][j][t0+t], only live j-tiles ----
    const int g   = lane >> 2;
    const int tig = lane & 3;
    #pragma unroll
    for (int mt = 0; mt < 4; ++mt) {
        if (jbase + mt * 16 < ql) {
            const int j = jbase + mt * 16 + g;
            #pragma unroll
            for (int nt = 0; nt < 4; ++nt) {
                const int t = t0 + tbase + nt * 8 + tig * 2;
                float* p0 = g_sim + ((size_t)(b * JLEN + j)) * TLEN + t;
                *reinterpret_cast<float2*>(p0) = make_float2(acc[mt][nt][0], acc[mt][nt][1]);
                *reinterpret_cast<float2*>(p0 + 8 * TLEN) = make_float2(acc[mt][nt][2], acc[mt][nt][3]);
            }
        }
    }
}

// ---------------------------------------------------------------------------
// Kernel 2: per (b, j<qlen): single-pass max + sum of exp (float4 row loads)
// ---------------------------------------------------------------------------
__device__ __forceinline__ float warpMax(float v) {
    #pragma unroll
    for (int o = 16; o > 0; o >>= 1) v = fmaxf(v, __shfl_xor_sync(0xffffffffu, v, o));
    return v;
}
__device__ __forceinline__ float warpSum(float v) {
    #pragma unroll
    for (int o = 16; o > 0; o >>= 1) v += __shfl_xor_sync(0xffffffffu, v, o);
    return v;
}

__global__ __launch_bounds__(256) void stats_kernel(
    const int* __restrict__ qlen,
    const int* __restrict__ clen)
{
    const int b = blockIdx.y;
    const int j = blockIdx.x;
    if (j >= qlen[b]) return;
    const int cl = clen[b];

    const float* row = g_sim + ((size_t)(b * JLEN + j)) * TLEN;
    const int tid = threadIdx.x;

    __shared__ float red[8];
    __shared__ float smax;

    // 2 float4 per thread covers 2048 floats; mask elements >= cl
    const float NEG = -3.4028235e38f;
    float v[8];
    #pragma unroll
    for (int i = 0; i < 2; ++i) {
        const int t4 = (tid + i * 256) * 4;
        float4 x = *reinterpret_cast<const float4*>(row + t4);
        v[i * 4 + 0] = (t4 + 0 < cl) ? x.x : NEG;
        v[i * 4 + 1] = (t4 + 1 < cl) ? x.y : NEG;
        v[i * 4 + 2] = (t4 + 2 < cl) ? x.z : NEG;
        v[i * 4 + 3] = (t4 + 3 < cl) ? x.w : NEG;
    }

    float m = v[0];
    #pragma unroll
    for (int i = 1; i < 8; ++i) m = fmaxf(m, v[i]);
    m = warpMax(m);
    if ((tid & 31) == 0) red[tid >> 5] = m;
    __syncthreads();
    if (tid == 0) {
        float mm = red[0];
        #pragma unroll
        for (int i = 1; i < 8; ++i) mm = fmaxf(mm, red[i]);
        smax = mm;
    }
    __syncthreads();
    m = smax;

    float s = 0.0f;
    #pragma unroll
    for (int i = 0; i < 8; ++i) s += __expf(v[i] - m);   // dead lanes underflow to 0
    s = warpSum(s);
    if ((tid & 31) == 0) red[tid >> 5] = s;
    __syncthreads();
    if (tid == 0) {
        float ss = 0.0f;
        #pragma unroll
        for (int i = 0; i < 8; ++i) ss += red[i];
        g_max[b * JLEN + j]    = m;
        g_invden[b * JLEN + j] = 1.0f / ss;
    }
}

// ---------------------------------------------------------------------------
// Kernel 3: out[b,t] = sum_{j<qlen} exp(sim[b][j][t]-max)*invden (t<clen), else 0
// Each thread owns 4 consecutive t (float4 loads, 4 independent chains).
// ---------------------------------------------------------------------------
__global__ __launch_bounds__(128) void out_kernel(
    const int* __restrict__ qlen,
    const int* __restrict__ clen,
    float* __restrict__ out)
{
    const int b  = blockIdx.y;
    const int t4 = (blockIdx.x * 128 + threadIdx.x) * 4;
    const int ql = qlen[b];
    const int cl = clen[b];

    __shared__ float sm[JLEN];
    __shared__ float sd[JLEN];
    for (int jj = threadIdx.x; jj < ql; jj += 128) {
        sm[jj] = g_max[b * JLEN + jj];
        sd[jj] = g_invden[b * JLEN + jj];
    }
    __syncthreads();

    float a0 = 0.0f, a1 = 0.0f, a2 = 0.0f, a3 = 0.0f;
    if (t4 < cl) {
        const float* base = g_sim + (size_t)b * JLEN * TLEN + t4;
        #pragma unroll 2
        for (int jj = 0; jj < ql; ++jj) {
            const float4 vv = *reinterpret_cast<const float4*>(base + (size_t)jj * TLEN);
            const float mj = sm[jj], dj = sd[jj];
            a0 += __expf(vv.x - mj) * dj;
            a1 += __expf(vv.y - mj) * dj;
            a2 += __expf(vv.z - mj) * dj;
            a3 += __expf(vv.w - mj) * dj;
        }
    }
    float4 o;
    o.x = (t4 + 0 < cl) ? a0 : 0.0f;
    o.y = (t4 + 1 < cl) ? a1 : 0.0f;
    o.z = (t4 + 2 < cl) ? a2 : 0.0f;
    o.w = (t4 + 3 < cl) ? a3 : 0.0f;
    *reinterpret_cast<float4*>(out + b * TLEN + t4) = o;
}

// ---------------------------------------------------------------------------
extern "C" void kernel_launch(void* const* d_in, const int* in_sizes, int n_in,
                              void* d_out, int out_size)
{
    const float* question = (const float*)d_in[0];
    const float* context  = (const float*)d_in[1];
    const int*   qlen     = (const int*)d_in[2];
    const int*   clen     = (const int*)d_in[3];
    const float* weight   = (const float*)d_in[4];
    float* out = (float*)d_out;

    cudaFuncSetAttribute(gemm_kernel, cudaFuncAttributeMaxDynamicSharedMemorySize, SM_TOTAL);

    prep_kernel<<<BATCH * JLEN, 128>>>(question, weight);

    dim3 g1(TLEN / TT, BATCH);              // 16 x 64
    gemm_kernel<<<g1, 256, SM_TOTAL>>>(context, qlen, clen);

    dim3 g2(JLEN, BATCH);                   // 128 x 64
    stats_kernel<<<g2, 256>>>(qlen, clen);

    dim3 g3(TLEN / 512, BATCH);             // 4 x 64
    out_kernel<<<g3, 128>>>(qlen, clen, out);
}

// round 10
// speedup vs baseline: 1.0432x; 1.0432x over previous
#include <cuda_runtime.h>
#include <cuda_bf16.h>
#include <cstdint>

#define BATCH 64
#define TLEN 2048
#define JLEN 128
#define DDIM 512

#define TT   128              // t per CTA (N tile)
#define KC   64               // k per chunk (64 bf16 = 128B row, SW128 atom)

// smem offsets (bytes) within 64KB dynamic smem
#define A_HI 0
#define A_LO 16384
#define B_HI 32768
#define B_LO 49152
#define SM_TOTAL 65536

#define SWZ128(off) ((off) ^ (((off) >> 3) & 0x70))

// Scratch
__device__ float g_sim[(size_t)BATCH * JLEN * TLEN];   // sim, then exp(sim - max) after stats
__device__ float g_max[BATCH * JLEN];
__device__ float g_invden[BATCH * JLEN];
__device__ __nv_bfloat16 g_qhi[(size_t)BATCH * JLEN * DDIM];  // (question*w) hi
__device__ __nv_bfloat16 g_qlo[(size_t)BATCH * JLEN * DDIM];  // (question*w) lo

// ---------------------------------------------------------------------------
// helpers
// ---------------------------------------------------------------------------
__device__ __forceinline__ uint32_t smem_u32(const void* p) {
    uint32_t a;
    asm("{ .reg .u64 t; cvta.to.shared.u64 t, %1; cvt.u32.u64 %0, t; }" : "=r"(a) : "l"(p));
    return a;
}

#define LDSM_X4(R, ADDR) \
    asm volatile("ldmatrix.sync.aligned.m8n8.x4.shared.b16 {%0,%1,%2,%3}, [%4];" \
        : "=r"((R)[0]), "=r"((R)[1]), "=r"((R)[2]), "=r"((R)[3]) : "r"(ADDR))

#define CP_ASYNC16(dst, src) \
    asm volatile("cp.async.cg.shared.global [%0], [%1], 16;" :: "r"(dst), "l"(src))
#define CP_COMMIT() asm volatile("cp.async.commit_group;" ::: "memory")
#define CP_WAIT0()  asm volatile("cp.async.wait_group 0;" ::: "memory")

__device__ __forceinline__ void mma16816(float* d, const uint32_t* a, const uint32_t* b) {
    asm volatile(
        "mma.sync.aligned.m16n8k16.row.col.f32.bf16.bf16.f32 "
        "{%0,%1,%2,%3}, {%4,%5,%6,%7}, {%8,%9}, {%0,%1,%2,%3};"
        : "+f"(d[0]), "+f"(d[1]), "+f"(d[2]), "+f"(d[3])
        : "r"(a[0]), "r"(a[1]), "r"(a[2]), "r"(a[3]), "r"(b[0]), "r"(b[1]));
}

__device__ __forceinline__ uint32_t pack2bf(float a, float b) {
    __nv_bfloat16 ha = __float2bfloat16(a);
    __nv_bfloat16 hb = __float2bfloat16(b);
    return (uint32_t)__bfloat16_as_ushort(ha) | ((uint32_t)__bfloat16_as_ushort(hb) << 16);
}

__device__ __forceinline__ void split4(const float4 v, uint32_t& h01, uint32_t& h23,
                                       uint32_t& l01, uint32_t& l23) {
    __nv_bfloat16 h0 = __float2bfloat16(v.x);
    __nv_bfloat16 h1 = __float2bfloat16(v.y);
    __nv_bfloat16 h2 = __float2bfloat16(v.z);
    __nv_bfloat16 h3 = __float2bfloat16(v.w);
    float r0 = v.x - __bfloat162float(h0);
    float r1 = v.y - __bfloat162float(h1);
    float r2 = v.z - __bfloat162float(h2);
    float r3 = v.w - __bfloat162float(h3);
    h01 = (uint32_t)__bfloat16_as_ushort(h0) | ((uint32_t)__bfloat16_as_ushort(h1) << 16);
    h23 = (uint32_t)__bfloat16_as_ushort(h2) | ((uint32_t)__bfloat16_as_ushort(h3) << 16);
    l01 = pack2bf(r0, r1);
    l23 = pack2bf(r2, r3);
}

// ---------------------------------------------------------------------------
// Kernel 0: split (question * w) into bf16 hi/lo global scratch
// ---------------------------------------------------------------------------
__global__ __launch_bounds__(128) void prep_kernel(
    const float* __restrict__ question,
    const float* __restrict__ weight)
{
    const int row = blockIdx.x;            // b*128 + j
    const int k4  = threadIdx.x * 4;
    const float4 q = __ldg(reinterpret_cast<const float4*>(question + (size_t)row * DDIM + k4));
    const float4 w = __ldg(reinterpret_cast<const float4*>(weight + k4));
    float4 v = make_float4(q.x * w.x, q.y * w.y, q.z * w.z, q.w * w.w);
    uint32_t h01, h23, l01, l23;
    split4(v, h01, h23, l01, l23);
    *reinterpret_cast<uint2*>(g_qhi + (size_t)row * DDIM + k4) = make_uint2(h01, h23);
    *reinterpret_cast<uint2*>(g_qlo + (size_t)row * DDIM + k4) = make_uint2(l01, l23);
}

// ---------------------------------------------------------------------------
// Kernel 1: HMMA GEMM. CTA = (t-tile of 128, b). Output D[j<ql(128)][t=128].
// 3-pass bf16 split, fp32 accum. 8 warps = 2(j) x 4(t); warp: 4 m16 x 4 n8.
// ---------------------------------------------------------------------------
__global__ __launch_bounds__(256) void gemm_kernel(
    const float* __restrict__ context,
    const int* __restrict__ qlen,
    const int* __restrict__ clen)
{
    extern __shared__ __align__(1024) char smem[];
    const int b  = blockIdx.y;
    const int t0 = blockIdx.x * TT;
    if (t0 >= clen[b]) return;
    const int ql = qlen[b];
    const int qlr = (ql + 15) & ~15;

    const uint32_t sb = smem_u32(smem);
    const int tid  = threadIdx.x;
    const int lane = tid & 31;
    const int wid  = tid >> 5;

    const int jbase = (wid & 1) << 6;
    const int tbase = (wid >> 1) << 5;

    const int r    = lane & 7;
    const int quad = lane >> 3;

    float acc[4][4][4];
    #pragma unroll
    for (int mt = 0; mt < 4; ++mt)
        #pragma unroll
        for (int nt = 0; nt < 4; ++nt)
            #pragma unroll
            for (int i = 0; i < 4; ++i) acc[mt][nt][i] = 0.0f;

    for (int kb = 0; kb < DDIM; kb += KC) {
        // ---- stage A via cp.async (bf16 hi/lo) : rows < qlr ----
        #pragma unroll
        for (int it = 0; it < 4; ++it) {
            const int idx = tid + it * 256;
            const int row = idx >> 3;
            const int u   = idx & 7;
            if (row < qlr) {
                const size_t src = ((size_t)(b * JLEN + row)) * DDIM + kb + u * 8;
                const uint32_t off = SWZ128((uint32_t)(row * 128 + u * 16));
                CP_ASYNC16(sb + A_HI + off, g_qhi + src);
                CP_ASYNC16(sb + A_LO + off, g_qlo + src);
            }
        }
        CP_COMMIT();

        // ---- stage B (context fp32 -> bf16 split) ----
        #pragma unroll
        for (int it = 0; it < 8; ++it) {
            const int idx = tid + it * 256;
            const int row = idx >> 4;
            const int u   = idx & 15;
            const float4 c = __ldg(reinterpret_cast<const float4*>(
                context + ((size_t)(b * TLEN + t0 + row)) * DDIM + kb + u * 4));
            uint32_t h01, h23, l01, l23;
            split4(c, h01, h23, l01, l23);
            const uint32_t off = SWZ128((uint32_t)(row * 128 + u * 8));
            *reinterpret_cast<uint2*>(smem + B_HI + off) = make_uint2(h01, h23);
            *reinterpret_cast<uint2*>(smem + B_LO + off) = make_uint2(l01, l23);
        }
        CP_WAIT0();
        __syncthreads();

        // ---- compute: 4 k16-steps ----
        #pragma unroll
        for (int ks = 0; ks < 4; ++ks) {
            uint32_t bh[8], bl[8];
            #pragma unroll
            for (int p = 0; p < 2; ++p) {
                const int tile  = p * 2 + (quad >> 1);
                const int khalf = quad & 1;
                const int rowt  = tbase + tile * 8 + r;
                const uint32_t off = SWZ128((uint32_t)(rowt * 128 + ks * 32 + khalf * 16));
                LDSM_X4(bh + p * 4, sb + B_HI + off);
                LDSM_X4(bl + p * 4, sb + B_LO + off);
            }
            #pragma unroll
            for (int mt = 0; mt < 4; ++mt) {
                if (jbase + mt * 16 < ql) {
                    const int rowa = jbase + mt * 16 + ((quad & 1) << 3) + r;
                    const uint32_t off = SWZ128((uint32_t)(rowa * 128 + ks * 32 + ((quad >> 1) << 4)));
                    uint32_t ah[4], al[4];
                    LDSM_X4(ah, sb + A_HI + off);
                    LDSM_X4(al, sb + A_LO + off);
                    #pragma unroll
                    for (int nt = 0; nt < 4; ++nt) {
                        mma16816(acc[mt][nt], ah, bh + nt * 2);
                        mma16816(acc[mt][nt], al, bh + nt * 2);
                        mma16816(acc[mt][nt], ah, bl + nt * 2);
                    }
                }
            }
        }
        __syncthreads();
    }

    // ---- epilogue ----
    const int g   = lane >> 2;
    const int tig = lane & 3;
    #pragma unroll
    for (int mt = 0; mt < 4; ++mt) {
        if (jbase + mt * 16 < ql) {
            const int j = jbase + mt * 16 + g;
            #pragma unroll
            for (int nt = 0; nt < 4; ++nt) {
                const int t = t0 + tbase + nt * 8 + tig * 2;
                float* p0 = g_sim + ((size_t)(b * JLEN + j)) * TLEN + t;
                *reinterpret_cast<float2*>(p0) = make_float2(acc[mt][nt][0], acc[mt][nt][1]);
                *reinterpret_cast<float2*>(p0 + 8 * TLEN) = make_float2(acc[mt][nt][2], acc[mt][nt][3]);
            }
        }
    }
}

// ---------------------------------------------------------------------------
// Kernel 2: per (b, j<qlen): max + sum of exp over t<clen, AND store
// p = exp(sim - max) back into g_sim (zeros beyond clen). Stores 1/sum.
// ---------------------------------------------------------------------------
__device__ __forceinline__ float warpMax(float v) {
    #pragma unroll
    for (int o = 16; o > 0; o >>= 1) v = fmaxf(v, __shfl_xor_sync(0xffffffffu, v, o));
    return v;
}
__device__ __forceinline__ float warpSum(float v) {
    #pragma unroll
    for (int o = 16; o > 0; o >>= 1) v += __shfl_xor_sync(0xffffffffu, v, o);
    return v;
}

__global__ __launch_bounds__(256) void stats_kernel(
    const int* __restrict__ qlen,
    const int* __restrict__ clen)
{
    const int b = blockIdx.y;
    const int j = blockIdx.x;
    if (j >= qlen[b]) return;
    const int cl = clen[b];

    float* row = g_sim + ((size_t)(b * JLEN + j)) * TLEN;
    const int tid = threadIdx.x;

    __shared__ float red[8];
    __shared__ float smax;

    const float NEG = -3.4028235e38f;
    float v[8];
    #pragma unroll
    for (int i = 0; i < 2; ++i) {
        const int t4 = (tid + i * 256) * 4;
        float4 x = *reinterpret_cast<const float4*>(row + t4);
        v[i * 4 + 0] = (t4 + 0 < cl) ? x.x : NEG;
        v[i * 4 + 1] = (t4 + 1 < cl) ? x.y : NEG;
        v[i * 4 + 2] = (t4 + 2 < cl) ? x.z : NEG;
        v[i * 4 + 3] = (t4 + 3 < cl) ? x.w : NEG;
    }

    float m = v[0];
    #pragma unroll
    for (int i = 1; i < 8; ++i) m = fmaxf(m, v[i]);
    m = warpMax(m);
    if ((tid & 31) == 0) red[tid >> 5] = m;
    __syncthreads();
    if (tid == 0) {
        float mm = red[0];
        #pragma unroll
        for (int i = 1; i < 8; ++i) mm = fmaxf(mm, red[i]);
        smax = mm;
    }
    __syncthreads();
    m = smax;

    // exp once; keep values, store them back (dead lanes -> exp underflows to 0)
    float e[8];
    float s = 0.0f;
    #pragma unroll
    for (int i = 0; i < 8; ++i) { e[i] = __expf(v[i] - m); s += e[i]; }

    #pragma unroll
    for (int i = 0; i < 2; ++i) {
        const int t4 = (tid + i * 256) * 4;
        *reinterpret_cast<float4*>(row + t4) =
            make_float4(e[i * 4 + 0], e[i * 4 + 1], e[i * 4 + 2], e[i * 4 + 3]);
    }

    s = warpSum(s);
    if ((tid & 31) == 0) red[tid >> 5] = s;
    __syncthreads();
    if (tid == 0) {
        float ss = 0.0f;
        #pragma unroll
        for (int i = 0; i < 8; ++i) ss += red[i];
        g_invden[b * JLEN + j] = 1.0f / ss;
    }
}

// ---------------------------------------------------------------------------
// Kernel 3: out[b,t] = sum_{j<qlen} p[j][t] * invden[j]  (pure FMA, no exp)
// p beyond clen is 0, so masking is automatic. 4 t per thread, float4.
// ---------------------------------------------------------------------------
__global__ __launch_bounds__(256) void out_kernel(
    const int* __restrict__ qlen,
    float* __restrict__ out)
{
    const int b  = blockIdx.y;
    const int t4 = (blockIdx.x * 256 + threadIdx.x) * 4;
    const int ql = qlen[b];

    __shared__ float sd[JLEN];
    for (int jj = threadIdx.x; jj < ql; jj += 256) sd[jj] = g_invden[b * JLEN + jj];
    __syncthreads();

    float a0 = 0.0f, a1 = 0.0f, a2 = 0.0f, a3 = 0.0f;
    const float* base = g_sim + (size_t)b * JLEN * TLEN + t4;
    #pragma unroll 4
    for (int jj = 0; jj < ql; ++jj) {
        const float4 vv = *reinterpret_cast<const float4*>(base + (size_t)jj * TLEN);
        const float dj = sd[jj];
        a0 += vv.x * dj;
        a1 += vv.y * dj;
        a2 += vv.z * dj;
        a3 += vv.w * dj;
    }
    *reinterpret_cast<float4*>(out + b * TLEN + t4) = make_float4(a0, a1, a2, a3);
}

// ---------------------------------------------------------------------------
extern "C" void kernel_launch(void* const* d_in, const int* in_sizes, int n_in,
                              void* d_out, int out_size)
{
    const float* question = (const float*)d_in[0];
    const float* context  = (const float*)d_in[1];
    const int*   qlen     = (const int*)d_in[2];
    const int*   clen     = (const int*)d_in[3];
    const float* weight   = (const float*)d_in[4];
    float* out = (float*)d_out;

    cudaFuncSetAttribute(gemm_kernel, cudaFuncAttributeMaxDynamicSharedMemorySize, SM_TOTAL);

    prep_kernel<<<BATCH * JLEN, 128>>>(question, weight);

    dim3 g1(TLEN / TT, BATCH);              // 16 x 64
    gemm_kernel<<<g1, 256, SM_TOTAL>>>(context, qlen, clen);

    dim3 g2(JLEN, BATCH);                   // 128 x 64
    stats_kernel<<<g2, 256>>>(qlen, clen);

    dim3 g3(TLEN / 1024, BATCH);            // 2 x 64
    out_kernel<<<g3, 256>>>(qlen, out);
}

// round 11
// speedup vs baseline: 1.0897x; 1.0446x over previous
#include <cuda_runtime.h>
#include <cuda_bf16.h>
#include <cuda_fp16.h>
#include <cstdint>

#define BATCH 64
#define TLEN 2048
#define JLEN 128
#define DDIM 512

#define TT   128              // t per CTA (N tile)
#define KC   64               // k per chunk (64 bf16 = 128B row, SW128 atom)

// smem offsets (bytes) within 64KB dynamic smem
#define A_HI 0
#define A_LO 16384
#define B_HI 32768
#define B_LO 49152
#define SM_TOTAL 65536

#define NJC 8                 // j-chunks in out pass
#define JCW (JLEN / NJC)      // 16 j per chunk

#define SWZ128(off) ((off) ^ (((off) >> 3) & 0x70))

// Scratch
__device__ float g_sim[(size_t)BATCH * JLEN * TLEN];           // raw logits
__device__ __half g_p[(size_t)BATCH * JLEN * TLEN];            // exp(sim-max), fp16
__device__ float g_part[(size_t)BATCH * NJC * TLEN];           // out partials
__device__ float g_invden[BATCH * JLEN];
__device__ __nv_bfloat16 g_qhi[(size_t)BATCH * JLEN * DDIM];   // (question*w) hi
__device__ __nv_bfloat16 g_qlo[(size_t)BATCH * JLEN * DDIM];   // (question*w) lo

// ---------------------------------------------------------------------------
// helpers
// ---------------------------------------------------------------------------
__device__ __forceinline__ uint32_t smem_u32(const void* p) {
    uint32_t a;
    asm("{ .reg .u64 t; cvta.to.shared.u64 t, %1; cvt.u32.u64 %0, t; }" : "=r"(a) : "l"(p));
    return a;
}

#define LDSM_X4(R, ADDR) \
    asm volatile("ldmatrix.sync.aligned.m8n8.x4.shared.b16 {%0,%1,%2,%3}, [%4];" \
        : "=r"((R)[0]), "=r"((R)[1]), "=r"((R)[2]), "=r"((R)[3]) : "r"(ADDR))

#define CP_ASYNC16(dst, src) \
    asm volatile("cp.async.cg.shared.global [%0], [%1], 16;" :: "r"(dst), "l"(src))
#define CP_COMMIT() asm volatile("cp.async.commit_group;" ::: "memory")
#define CP_WAIT0()  asm volatile("cp.async.wait_group 0;" ::: "memory")

__device__ __forceinline__ void mma16816(float* d, const uint32_t* a, const uint32_t* b) {
    asm volatile(
        "mma.sync.aligned.m16n8k16.row.col.f32.bf16.bf16.f32 "
        "{%0,%1,%2,%3}, {%4,%5,%6,%7}, {%8,%9}, {%0,%1,%2,%3};"
        : "+f"(d[0]), "+f"(d[1]), "+f"(d[2]), "+f"(d[3])
        : "r"(a[0]), "r"(a[1]), "r"(a[2]), "r"(a[3]), "r"(b[0]), "r"(b[1]));
}

__device__ __forceinline__ uint32_t pack2bf(float a, float b) {
    __nv_bfloat16 ha = __float2bfloat16(a);
    __nv_bfloat16 hb = __float2bfloat16(b);
    return (uint32_t)__bfloat16_as_ushort(ha) | ((uint32_t)__bfloat16_as_ushort(hb) << 16);
}

__device__ __forceinline__ void split4(const float4 v, uint32_t& h01, uint32_t& h23,
                                       uint32_t& l01, uint32_t& l23) {
    __nv_bfloat16 h0 = __float2bfloat16(v.x);
    __nv_bfloat16 h1 = __float2bfloat16(v.y);
    __nv_bfloat16 h2 = __float2bfloat16(v.z);
    __nv_bfloat16 h3 = __float2bfloat16(v.w);
    float r0 = v.x - __bfloat162float(h0);
    float r1 = v.y - __bfloat162float(h1);
    float r2 = v.z - __bfloat162float(h2);
    float r3 = v.w - __bfloat162float(h3);
    h01 = (uint32_t)__bfloat16_as_ushort(h0) | ((uint32_t)__bfloat16_as_ushort(h1) << 16);
    h23 = (uint32_t)__bfloat16_as_ushort(h2) | ((uint32_t)__bfloat16_as_ushort(h3) << 16);
    l01 = pack2bf(r0, r1);
    l23 = pack2bf(r2, r3);
}

// ---------------------------------------------------------------------------
// Kernel 0: split (question * w) into bf16 hi/lo global scratch
// ---------------------------------------------------------------------------
__global__ __launch_bounds__(128) void prep_kernel(
    const float* __restrict__ question,
    const float* __restrict__ weight)
{
    const int row = blockIdx.x;            // b*128 + j
    const int k4  = threadIdx.x * 4;
    const float4 q = __ldg(reinterpret_cast<const float4*>(question + (size_t)row * DDIM + k4));
    const float4 w = __ldg(reinterpret_cast<const float4*>(weight + k4));
    float4 v = make_float4(q.x * w.x, q.y * w.y, q.z * w.z, q.w * w.w);
    uint32_t h01, h23, l01, l23;
    split4(v, h01, h23, l01, l23);
    *reinterpret_cast<uint2*>(g_qhi + (size_t)row * DDIM + k4) = make_uint2(h01, h23);
    *reinterpret_cast<uint2*>(g_qlo + (size_t)row * DDIM + k4) = make_uint2(l01, l23);
}

// ---------------------------------------------------------------------------
// Kernel 1: HMMA GEMM. CTA = (t-tile of 128, b). Output D[j<ql(128)][t=128].
// 3-pass bf16 split, fp32 accum. 8 warps = 2(j) x 4(t); warp: 4 m16 x 4 n8.
// ---------------------------------------------------------------------------
__global__ __launch_bounds__(256) void gemm_kernel(
    const float* __restrict__ context,
    const int* __restrict__ qlen,
    const int* __restrict__ clen)
{
    extern __shared__ __align__(1024) char smem[];
    const int b  = blockIdx.y;
    const int t0 = blockIdx.x * TT;
    if (t0 >= clen[b]) return;
    const int ql = qlen[b];
    const int qlr = (ql + 15) & ~15;

    const uint32_t sb = smem_u32(smem);
    const int tid  = threadIdx.x;
    const int lane = tid & 31;
    const int wid  = tid >> 5;

    const int jbase = (wid & 1) << 6;
    const int tbase = (wid >> 1) << 5;

    const int r    = lane & 7;
    const int quad = lane >> 3;

    float acc[4][4][4];
    #pragma unroll
    for (int mt = 0; mt < 4; ++mt)
        #pragma unroll
        for (int nt = 0; nt < 4; ++nt)
            #pragma unroll
            for (int i = 0; i < 4; ++i) acc[mt][nt][i] = 0.0f;

    for (int kb = 0; kb < DDIM; kb += KC) {
        // ---- stage A via cp.async (bf16 hi/lo) : rows < qlr ----
        #pragma unroll
        for (int it = 0; it < 4; ++it) {
            const int idx = tid + it * 256;
            const int row = idx >> 3;
            const int u   = idx & 7;
            if (row < qlr) {
                const size_t src = ((size_t)(b * JLEN + row)) * DDIM + kb + u * 8;
                const uint32_t off = SWZ128((uint32_t)(row * 128 + u * 16));
                CP_ASYNC16(sb + A_HI + off, g_qhi + src);
                CP_ASYNC16(sb + A_LO + off, g_qlo + src);
            }
        }
        CP_COMMIT();

        // ---- stage B (context fp32 -> bf16 split) ----
        #pragma unroll
        for (int it = 0; it < 8; ++it) {
            const int idx = tid + it * 256;
            const int row = idx >> 4;
            const int u   = idx & 15;
            const float4 c = __ldg(reinterpret_cast<const float4*>(
                context + ((size_t)(b * TLEN + t0 + row)) * DDIM + kb + u * 4));
            uint32_t h01, h23, l01, l23;
            split4(c, h01, h23, l01, l23);
            const uint32_t off = SWZ128((uint32_t)(row * 128 + u * 8));
            *reinterpret_cast<uint2*>(smem + B_HI + off) = make_uint2(h01, h23);
            *reinterpret_cast<uint2*>(smem + B_LO + off) = make_uint2(l01, l23);
        }
        CP_WAIT0();
        __syncthreads();

        // ---- compute: 4 k16-steps ----
        #pragma unroll
        for (int ks = 0; ks < 4; ++ks) {
            uint32_t bh[8], bl[8];
            #pragma unroll
            for (int p = 0; p < 2; ++p) {
                const int tile  = p * 2 + (quad >> 1);
                const int khalf = quad & 1;
                const int rowt  = tbase + tile * 8 + r;
                const uint32_t off = SWZ128((uint32_t)(rowt * 128 + ks * 32 + khalf * 16));
                LDSM_X4(bh + p * 4, sb + B_HI + off);
                LDSM_X4(bl + p * 4, sb + B_LO + off);
            }
            #pragma unroll
            for (int mt = 0; mt < 4; ++mt) {
                if (jbase + mt * 16 < ql) {
                    const int rowa = jbase + mt * 16 + ((quad & 1) << 3) + r;
                    const uint32_t off = SWZ128((uint32_t)(rowa * 128 + ks * 32 + ((quad >> 1) << 4)));
                    uint32_t ah[4], al[4];
                    LDSM_X4(ah, sb + A_HI + off);
                    LDSM_X4(al, sb + A_LO + off);
                    #pragma unroll
                    for (int nt = 0; nt < 4; ++nt) {
                        mma16816(acc[mt][nt], ah, bh + nt * 2);
                        mma16816(acc[mt][nt], al, bh + nt * 2);
                        mma16816(acc[mt][nt], ah, bl + nt * 2);
                    }
                }
            }
        }
        __syncthreads();
    }

    // ---- epilogue ----
    const int g   = lane >> 2;
    const int tig = lane & 3;
    #pragma unroll
    for (int mt = 0; mt < 4; ++mt) {
        if (jbase + mt * 16 < ql) {
            const int j = jbase + mt * 16 + g;
            #pragma unroll
            for (int nt = 0; nt < 4; ++nt) {
                const int t = t0 + tbase + nt * 8 + tig * 2;
                float* p0 = g_sim + ((size_t)(b * JLEN + j)) * TLEN + t;
                *reinterpret_cast<float2*>(p0) = make_float2(acc[mt][nt][0], acc[mt][nt][1]);
                *reinterpret_cast<float2*>(p0 + 8 * TLEN) = make_float2(acc[mt][nt][2], acc[mt][nt][3]);
            }
        }
    }
}

// ---------------------------------------------------------------------------
// Kernel 2: per (b, j<qlen): block max + sum of exp over t<clen;
// stores p = exp(sim-max) as fp16 into g_p (zeros beyond clen) and 1/sum.
// Loads beyond clen are skipped.
// ---------------------------------------------------------------------------
__device__ __forceinline__ float warpMax(float v) {
    #pragma unroll
    for (int o = 16; o > 0; o >>= 1) v = fmaxf(v, __shfl_xor_sync(0xffffffffu, v, o));
    return v;
}
__device__ __forceinline__ float warpSum(float v) {
    #pragma unroll
    for (int o = 16; o > 0; o >>= 1) v += __shfl_xor_sync(0xffffffffu, v, o);
    return v;
}

__global__ __launch_bounds__(256) void stats_kernel(
    const int* __restrict__ qlen,
    const int* __restrict__ clen)
{
    const int b = blockIdx.y;
    const int j = blockIdx.x;
    if (j >= qlen[b]) return;
    const int cl = clen[b];

    const float* row = g_sim + ((size_t)(b * JLEN + j)) * TLEN;
    __half* prow = g_p + ((size_t)(b * JLEN + j)) * TLEN;
    const int tid = threadIdx.x;

    __shared__ float red[8];
    __shared__ float smax;

    const float NEG = -3.4028235e38f;
    float v[8];
    #pragma unroll
    for (int i = 0; i < 2; ++i) {
        const int t4 = (tid + i * 256) * 4;
        float4 x = make_float4(NEG, NEG, NEG, NEG);
        if (t4 < cl) x = *reinterpret_cast<const float4*>(row + t4);
        v[i * 4 + 0] = (t4 + 0 < cl) ? x.x : NEG;
        v[i * 4 + 1] = (t4 + 1 < cl) ? x.y : NEG;
        v[i * 4 + 2] = (t4 + 2 < cl) ? x.z : NEG;
        v[i * 4 + 3] = (t4 + 3 < cl) ? x.w : NEG;
    }

    float m = v[0];
    #pragma unroll
    for (int i = 1; i < 8; ++i) m = fmaxf(m, v[i]);
    m = warpMax(m);
    if ((tid & 31) == 0) red[tid >> 5] = m;
    __syncthreads();
    if (tid == 0) {
        float mm = red[0];
        #pragma unroll
        for (int i = 1; i < 8; ++i) mm = fmaxf(mm, red[i]);
        smax = mm;
    }
    __syncthreads();
    m = smax;

    float e[8];
    float s = 0.0f;
    #pragma unroll
    for (int i = 0; i < 8; ++i) { e[i] = __expf(v[i] - m); s += e[i]; }  // dead -> 0

    // store p as fp16 (full row: zeros beyond cl keep g_p well-defined)
    #pragma unroll
    for (int i = 0; i < 2; ++i) {
        const int t4 = (tid + i * 256) * 4;
        __half2 h01 = __floats2half2_rn(e[i * 4 + 0], e[i * 4 + 1]);
        __half2 h23 = __floats2half2_rn(e[i * 4 + 2], e[i * 4 + 3]);
        uint2 u;
        u.x = *reinterpret_cast<uint32_t*>(&h01);
        u.y = *reinterpret_cast<uint32_t*>(&h23);
        *reinterpret_cast<uint2*>(prow + t4) = u;
    }

    s = warpSum(s);
    if ((tid & 31) == 0) red[tid >> 5] = s;
    __syncthreads();
    if (tid == 0) {
        float ss = 0.0f;
        #pragma unroll
        for (int i = 0; i < 8; ++i) ss += red[i];
        g_invden[b * JLEN + j] = 1.0f / ss;
    }
}

// ---------------------------------------------------------------------------
// Kernel 3: partial out over a j-chunk of 16.
// g_part[b][jc][t] = sum_{j in chunk, j<ql} p[j][t] * invden[j]
// Thread owns 8 consecutive t (one uint4 of fp16 per j).
// ---------------------------------------------------------------------------
__global__ __launch_bounds__(256) void out_part_kernel(
    const int* __restrict__ qlen,
    const int* __restrict__ clen)
{
    const int b  = blockIdx.y;
    const int jc = blockIdx.x;
    const int ql = qlen[b];
    const int cl = clen[b];
    const int j0 = jc * JCW;
    const int t8 = threadIdx.x * 8;

    __shared__ float sd[JCW];
    if (threadIdx.x < JCW) {
        const int j = j0 + threadIdx.x;
        sd[threadIdx.x] = (j < ql) ? g_invden[b * JLEN + j] : 0.0f;
    }
    __syncthreads();

    float a[8];
    #pragma unroll
    for (int i = 0; i < 8; ++i) a[i] = 0.0f;

    if (j0 < ql && t8 < cl) {
        const int nj = min(JCW, ql - j0);
        const __half* base = g_p + ((size_t)(b * JLEN + j0)) * TLEN + t8;
        for (int jj = 0; jj < nj; ++jj) {
            const uint4 u = *reinterpret_cast<const uint4*>(base + (size_t)jj * TLEN);
            const float dj = sd[jj];
            const __half2* h = reinterpret_cast<const __half2*>(&u);
            #pragma unroll
            for (int q = 0; q < 4; ++q) {
                const float2 f = __half22float2(h[q]);
                a[q * 2 + 0] += f.x * dj;
                a[q * 2 + 1] += f.y * dj;
            }
        }
    }

    float* part = g_part + ((size_t)(b * NJC + jc)) * TLEN + t8;
    *reinterpret_cast<float4*>(part)     = make_float4(a[0], a[1], a[2], a[3]);
    *reinterpret_cast<float4*>(part + 4) = make_float4(a[4], a[5], a[6], a[7]);
}

// ---------------------------------------------------------------------------
// Kernel 4: out[b][t] = sum_{jc} g_part[b][jc][t]
// ---------------------------------------------------------------------------
__global__ __launch_bounds__(256) void combine_kernel(float* __restrict__ out)
{
    const int idx = blockIdx.x * 256 + threadIdx.x;   // 0..32767
    const int b   = idx >> 9;                         // 512 float4 per batch
    const int t4  = (idx & 511) * 4;

    const float* p = g_part + ((size_t)b * NJC) * TLEN + t4;
    float4 s = make_float4(0.f, 0.f, 0.f, 0.f);
    #pragma unroll
    for (int jc = 0; jc < NJC; ++jc) {
        const float4 v = *reinterpret_cast<const float4*>(p + (size_t)jc * TLEN);
        s.x += v.x; s.y += v.y; s.z += v.z; s.w += v.w;
    }
    *reinterpret_cast<float4*>(out + (size_t)b * TLEN + t4) = s;
}

// ---------------------------------------------------------------------------
extern "C" void kernel_launch(void* const* d_in, const int* in_sizes, int n_in,
                              void* d_out, int out_size)
{
    const float* question = (const float*)d_in[0];
    const float* context  = (const float*)d_in[1];
    const int*   qlen     = (const int*)d_in[2];
    const int*   clen     = (const int*)d_in[3];
    const float* weight   = (const float*)d_in[4];
    float* out = (float*)d_out;

    cudaFuncSetAttribute(gemm_kernel, cudaFuncAttributeMaxDynamicSharedMemorySize, SM_TOTAL);

    prep_kernel<<<BATCH * JLEN, 128>>>(question, weight);

    dim3 g1(TLEN / TT, BATCH);              // 16 x 64
    gemm_kernel<<<g1, 256, SM_TOTAL>>>(context, qlen, clen);

    dim3 g2(JLEN, BATCH);                   // 128 x 64
    stats_kernel<<<g2, 256>>>(qlen, clen);

    dim3 g3(NJC, BATCH);                    // 8 x 64
    out_part_kernel<<<g3, 256>>>(qlen, clen);

    combine_kernel<<<BATCH * TLEN / 1024, 256>>>(out);   // 128 x 256
}

// round 12
// speedup vs baseline: 1.1533x; 1.0584x over previous
#include <cuda_runtime.h>
#include <cuda_bf16.h>
#include <cuda_fp16.h>
#include <cstdint>

#define BATCH 64
#define TLEN 2048
#define JLEN 128
#define DDIM 512

#define TT   128              // t per CTA (N tile)
#define KC   64               // k per chunk (64 bf16 = 128B row, SW128 atom)
#define NTILE (TLEN / TT)     // 16 t-tiles

// smem offsets (bytes) within 64KB dynamic smem
#define A_HI 0
#define A_LO 16384
#define B_HI 32768
#define B_LO 49152
#define SM_TOTAL 65536

#define NJC 8                 // j-chunks in out pass
#define JCW (JLEN / NJC)      // 16 j per chunk

#define SWZ128(off) ((off) ^ (((off) >> 3) & 0x70))

// Scratch
__device__ __half g_p[(size_t)BATCH * JLEN * TLEN];            // exp(sim - m_local), fp16
__device__ float g_m[(size_t)BATCH * JLEN * NTILE];            // per-tile local max
__device__ float g_s[(size_t)BATCH * JLEN * NTILE];            // per-tile local expsum
__device__ float g_factor[(size_t)BATCH * JLEN * NTILE];       // exp(m-M)/S
__device__ float g_part[(size_t)BATCH * NJC * TLEN];           // out partials
__device__ __nv_bfloat16 g_qhi[(size_t)BATCH * JLEN * DDIM];   // (question*w) hi
__device__ __nv_bfloat16 g_qlo[(size_t)BATCH * JLEN * DDIM];   // (question*w) lo

// ---------------------------------------------------------------------------
// helpers
// ---------------------------------------------------------------------------
__device__ __forceinline__ uint32_t smem_u32(const void* p) {
    uint32_t a;
    asm("{ .reg .u64 t; cvta.to.shared.u64 t, %1; cvt.u32.u64 %0, t; }" : "=r"(a) : "l"(p));
    return a;
}

#define LDSM_X4(R, ADDR) \
    asm volatile("ldmatrix.sync.aligned.m8n8.x4.shared.b16 {%0,%1,%2,%3}, [%4];" \
        : "=r"((R)[0]), "=r"((R)[1]), "=r"((R)[2]), "=r"((R)[3]) : "r"(ADDR))

#define CP_ASYNC16(dst, src) \
    asm volatile("cp.async.cg.shared.global [%0], [%1], 16;" :: "r"(dst), "l"(src))
#define CP_COMMIT() asm volatile("cp.async.commit_group;" ::: "memory")
#define CP_WAIT0()  asm volatile("cp.async.wait_group 0;" ::: "memory")

__device__ __forceinline__ void mma16816(float* d, const uint32_t* a, const uint32_t* b) {
    asm volatile(
        "mma.sync.aligned.m16n8k16.row.col.f32.bf16.bf16.f32 "
        "{%0,%1,%2,%3}, {%4,%5,%6,%7}, {%8,%9}, {%0,%1,%2,%3};"
        : "+f"(d[0]), "+f"(d[1]), "+f"(d[2]), "+f"(d[3])
        : "r"(a[0]), "r"(a[1]), "r"(a[2]), "r"(a[3]), "r"(b[0]), "r"(b[1]));
}

__device__ __forceinline__ uint32_t pack2bf(float a, float b) {
    __nv_bfloat16 ha = __float2bfloat16(a);
    __nv_bfloat16 hb = __float2bfloat16(b);
    return (uint32_t)__bfloat16_as_ushort(ha) | ((uint32_t)__bfloat16_as_ushort(hb) << 16);
}

__device__ __forceinline__ void split4(const float4 v, uint32_t& h01, uint32_t& h23,
                                       uint32_t& l01, uint32_t& l23) {
    __nv_bfloat16 h0 = __float2bfloat16(v.x);
    __nv_bfloat16 h1 = __float2bfloat16(v.y);
    __nv_bfloat16 h2 = __float2bfloat16(v.z);
    __nv_bfloat16 h3 = __float2bfloat16(v.w);
    float r0 = v.x - __bfloat162float(h0);
    float r1 = v.y - __bfloat162float(h1);
    float r2 = v.z - __bfloat162float(h2);
    float r3 = v.w - __bfloat162float(h3);
    h01 = (uint32_t)__bfloat16_as_ushort(h0) | ((uint32_t)__bfloat16_as_ushort(h1) << 16);
    h23 = (uint32_t)__bfloat16_as_ushort(h2) | ((uint32_t)__bfloat16_as_ushort(h3) << 16);
    l01 = pack2bf(r0, r1);
    l23 = pack2bf(r2, r3);
}

// ---------------------------------------------------------------------------
// Kernel 0: split (question * w) into bf16 hi/lo global scratch
// ---------------------------------------------------------------------------
__global__ __launch_bounds__(128) void prep_kernel(
    const float* __restrict__ question,
    const float* __restrict__ weight)
{
    const int row = blockIdx.x;            // b*128 + j
    const int k4  = threadIdx.x * 4;
    const float4 q = __ldg(reinterpret_cast<const float4*>(question + (size_t)row * DDIM + k4));
    const float4 w = __ldg(reinterpret_cast<const float4*>(weight + k4));
    float4 v = make_float4(q.x * w.x, q.y * w.y, q.z * w.z, q.w * w.w);
    uint32_t h01, h23, l01, l23;
    split4(v, h01, h23, l01, l23);
    *reinterpret_cast<uint2*>(g_qhi + (size_t)row * DDIM + k4) = make_uint2(h01, h23);
    *reinterpret_cast<uint2*>(g_qlo + (size_t)row * DDIM + k4) = make_uint2(l01, l23);
}

// ---------------------------------------------------------------------------
// Kernel 1: HMMA GEMM + fused local softmax epilogue.
// CTA = (t-tile of 128, b). 3-pass bf16 split, fp32 accum.
// Epilogue: per-j local max over this 128-t tile (masked by clen),
// p = exp(v - m_local) stored fp16 to g_p; (m_local, sum) -> g_m/g_s.
// ---------------------------------------------------------------------------
__global__ __launch_bounds__(256) void gemm_kernel(
    const float* __restrict__ context,
    const int* __restrict__ qlen,
    const int* __restrict__ clen)
{
    extern __shared__ __align__(1024) char smem[];
    const int b  = blockIdx.y;
    const int t0 = blockIdx.x * TT;
    const int cl = clen[b];
    if (t0 >= cl) return;
    const int ql = qlen[b];
    const int qlr = (ql + 15) & ~15;

    const uint32_t sb = smem_u32(smem);
    const int tid  = threadIdx.x;
    const int lane = tid & 31;
    const int wid  = tid >> 5;

    const int jbase = (wid & 1) << 6;
    const int tbase = (wid >> 1) << 5;

    const int r    = lane & 7;
    const int quad = lane >> 3;

    float acc[4][4][4];
    #pragma unroll
    for (int mt = 0; mt < 4; ++mt)
        #pragma unroll
        for (int nt = 0; nt < 4; ++nt)
            #pragma unroll
            for (int i = 0; i < 4; ++i) acc[mt][nt][i] = 0.0f;

    for (int kb = 0; kb < DDIM; kb += KC) {
        // ---- stage A via cp.async (bf16 hi/lo) : rows < qlr ----
        #pragma unroll
        for (int it = 0; it < 4; ++it) {
            const int idx = tid + it * 256;
            const int row = idx >> 3;
            const int u   = idx & 7;
            if (row < qlr) {
                const size_t src = ((size_t)(b * JLEN + row)) * DDIM + kb + u * 8;
                const uint32_t off = SWZ128((uint32_t)(row * 128 + u * 16));
                CP_ASYNC16(sb + A_HI + off, g_qhi + src);
                CP_ASYNC16(sb + A_LO + off, g_qlo + src);
            }
        }
        CP_COMMIT();

        // ---- stage B (context fp32 -> bf16 split) ----
        #pragma unroll
        for (int it = 0; it < 8; ++it) {
            const int idx = tid + it * 256;
            const int row = idx >> 4;
            const int u   = idx & 15;
            const float4 c = __ldg(reinterpret_cast<const float4*>(
                context + ((size_t)(b * TLEN + t0 + row)) * DDIM + kb + u * 4));
            uint32_t h01, h23, l01, l23;
            split4(c, h01, h23, l01, l23);
            const uint32_t off = SWZ128((uint32_t)(row * 128 + u * 8));
            *reinterpret_cast<uint2*>(smem + B_HI + off) = make_uint2(h01, h23);
            *reinterpret_cast<uint2*>(smem + B_LO + off) = make_uint2(l01, l23);
        }
        CP_WAIT0();
        __syncthreads();

        // ---- compute: 4 k16-steps ----
        #pragma unroll
        for (int ks = 0; ks < 4; ++ks) {
            uint32_t bh[8], bl[8];
            #pragma unroll
            for (int p = 0; p < 2; ++p) {
                const int tile  = p * 2 + (quad >> 1);
                const int khalf = quad & 1;
                const int rowt  = tbase + tile * 8 + r;
                const uint32_t off = SWZ128((uint32_t)(rowt * 128 + ks * 32 + khalf * 16));
                LDSM_X4(bh + p * 4, sb + B_HI + off);
                LDSM_X4(bl + p * 4, sb + B_LO + off);
            }
            #pragma unroll
            for (int mt = 0; mt < 4; ++mt) {
                if (jbase + mt * 16 < ql) {
                    const int rowa = jbase + mt * 16 + ((quad & 1) << 3) + r;
                    const uint32_t off = SWZ128((uint32_t)(rowa * 128 + ks * 32 + ((quad >> 1) << 4)));
                    uint32_t ah[4], al[4];
                    LDSM_X4(ah, sb + A_HI + off);
                    LDSM_X4(al, sb + A_LO + off);
                    #pragma unroll
                    for (int nt = 0; nt < 4; ++nt) {
                        mma16816(acc[mt][nt], ah, bh + nt * 2);
                        mma16816(acc[mt][nt], al, bh + nt * 2);
                        mma16816(acc[mt][nt], ah, bl + nt * 2);
                    }
                }
            }
        }
        __syncthreads();
    }

    // =================== fused softmax epilogue ===================
    // smem reuse (after final sync): red[4][128] partials, mfin[128] final max
    float* red  = reinterpret_cast<float*>(smem);          // 512 floats
    float* mfin = red + 512;                               // 128 floats

    const int g   = lane >> 2;     // 0..7 (row within 8-group)
    const int tig = lane & 3;      // 0..3 (t pair within group)
    const int tw  = wid >> 1;      // 0..3 (t-warp index)
    const float NEG = -3.4028235e38f;

    // ---- pass 1: local max per j-row over this tile (masked by cl) ----
    float mrow[8];
    #pragma unroll
    for (int mt = 0; mt < 4; ++mt) {
        #pragma unroll
        for (int h = 0; h < 2; ++h) {
            float mm = NEG;
            #pragma unroll
            for (int nt = 0; nt < 4; ++nt) {
                const int tg = t0 + tbase + nt * 8 + tig * 2;
                const float v0 = (tg     < cl) ? acc[mt][nt][h * 2 + 0] : NEG;
                const float v1 = (tg + 1 < cl) ? acc[mt][nt][h * 2 + 1] : NEG;
                mm = fmaxf(mm, fmaxf(v0, v1));
            }
            mrow[mt * 2 + h] = mm;
        }
    }
    #pragma unroll
    for (int i = 0; i < 8; ++i) {
        mrow[i] = fmaxf(mrow[i], __shfl_xor_sync(0xffffffffu, mrow[i], 1));
        mrow[i] = fmaxf(mrow[i], __shfl_xor_sync(0xffffffffu, mrow[i], 2));
    }
    if (tig == 0) {
        #pragma unroll
        for (int mt = 0; mt < 4; ++mt)
            #pragma unroll
            for (int h = 0; h < 2; ++h) {
                const int row = jbase + mt * 16 + h * 8 + g;
                red[tw * 128 + row] = mrow[mt * 2 + h];
            }
    }
    __syncthreads();
    if (tid < 128)
        mfin[tid] = fmaxf(fmaxf(red[tid], red[128 + tid]),
                          fmaxf(red[256 + tid], red[384 + tid]));
    __syncthreads();

    // ---- pass 2: exp, store p (fp16), per-row sums ----
    float srow[8];
    #pragma unroll
    for (int mt = 0; mt < 4; ++mt) {
        const bool live = (jbase + mt * 16 < ql);
        #pragma unroll
        for (int h = 0; h < 2; ++h) {
            const int row = jbase + mt * 16 + h * 8 + g;
            float s = 0.0f;
            if (live) {
                const float mref = mfin[row];
                __half* prow = g_p + ((size_t)(b * JLEN + row)) * TLEN;
                #pragma unroll
                for (int nt = 0; nt < 4; ++nt) {
                    const int tg = t0 + tbase + nt * 8 + tig * 2;
                    const float e0 = (tg     < cl) ? __expf(acc[mt][nt][h * 2 + 0] - mref) : 0.0f;
                    const float e1 = (tg + 1 < cl) ? __expf(acc[mt][nt][h * 2 + 1] - mref) : 0.0f;
                    s += e0 + e1;
                    *reinterpret_cast<__half2*>(prow + tg) = __floats2half2_rn(e0, e1);
                }
            }
            srow[mt * 2 + h] = s;
        }
    }
    #pragma unroll
    for (int i = 0; i < 8; ++i) {
        srow[i] += __shfl_xor_sync(0xffffffffu, srow[i], 1);
        srow[i] += __shfl_xor_sync(0xffffffffu, srow[i], 2);
    }
    __syncthreads();   // mfin reads done; red reuse safe
    if (tig == 0) {
        #pragma unroll
        for (int mt = 0; mt < 4; ++mt)
            #pragma unroll
            for (int h = 0; h < 2; ++h) {
                const int row = jbase + mt * 16 + h * 8 + g;
                red[tw * 128 + row] = srow[mt * 2 + h];
            }
    }
    __syncthreads();
    if (tid < 128) {
        const float S = red[tid] + red[128 + tid] + red[256 + tid] + red[384 + tid];
        const int tile = t0 >> 7;
        g_m[((size_t)(b * JLEN) + tid) * NTILE + tile] = mfin[tid];
        g_s[((size_t)(b * JLEN) + tid) * NTILE + tile] = S;
    }
}

// ---------------------------------------------------------------------------
// Kernel 2: combine tile stats -> factor[b][j][tile] = exp(m-M)/S_global
// ---------------------------------------------------------------------------
__global__ __launch_bounds__(256) void cstats_kernel(
    const int* __restrict__ qlen,
    const int* __restrict__ clen)
{
    const int idx = blockIdx.x * 256 + threadIdx.x;   // 0..8191 = b*128+j
    const int b = idx >> 7;
    const int j = idx & 127;
    const int ql = qlen[b];
    const int cl = clen[b];
    const int ntl = (cl + TT - 1) / TT;

    float f[NTILE];
    if (j < ql) {
        float mv[NTILE];
        float M = -3.4028235e38f;
        for (int k = 0; k < ntl; ++k) {
            mv[k] = g_m[(size_t)idx * NTILE + k];
            M = fmaxf(M, mv[k]);
        }
        float S = 0.0f;
        for (int k = 0; k < ntl; ++k) {
            mv[k] = __expf(mv[k] - M);
            S += g_s[(size_t)idx * NTILE + k] * mv[k];
        }
        const float inv = 1.0f / S;
        #pragma unroll
        for (int k = 0; k < NTILE; ++k)
            f[k] = (k < ntl) ? mv[k] * inv : 0.0f;
    } else {
        #pragma unroll
        for (int k = 0; k < NTILE; ++k) f[k] = 0.0f;
    }

    float* dst = g_factor + (size_t)idx * NTILE;
    #pragma unroll
    for (int q = 0; q < 4; ++q)
        *reinterpret_cast<float4*>(dst + q * 4) =
            make_float4(f[q * 4 + 0], f[q * 4 + 1], f[q * 4 + 2], f[q * 4 + 3]);
}

// ---------------------------------------------------------------------------
// Kernel 3: partial out over a j-chunk of 16.
// g_part[b][jc][t] = sum_{j in chunk} p[j][t] * factor[j][tile(t)]
// ---------------------------------------------------------------------------
__global__ __launch_bounds__(256) void out_part_kernel(
    const int* __restrict__ qlen,
    const int* __restrict__ clen)
{
    const int b  = blockIdx.y;
    const int jc = blockIdx.x;
    const int ql = qlen[b];
    const int cl = clen[b];
    const int j0 = jc * JCW;
    const int t8 = threadIdx.x * 8;

    __shared__ float sf[JCW][NTILE];
    {
        const int jj = threadIdx.x >> 4;
        const int k  = threadIdx.x & 15;
        sf[jj][k] = g_factor[((size_t)(b * JLEN + j0 + jj)) * NTILE + k];
    }
    __syncthreads();

    float a[8];
    #pragma unroll
    for (int i = 0; i < 8; ++i) a[i] = 0.0f;

    if (j0 < ql && t8 < cl) {
        const int tile = t8 >> 7;
        const int nj = min(JCW, ql - j0);
        const __half* base = g_p + ((size_t)(b * JLEN + j0)) * TLEN + t8;
        for (int jj = 0; jj < nj; ++jj) {
            const uint4 u = *reinterpret_cast<const uint4*>(base + (size_t)jj * TLEN);
            const float dj = sf[jj][tile];
            const __half2* h = reinterpret_cast<const __half2*>(&u);
            #pragma unroll
            for (int q = 0; q < 4; ++q) {
                const float2 fv = __half22float2(h[q]);
                a[q * 2 + 0] += fv.x * dj;
                a[q * 2 + 1] += fv.y * dj;
            }
        }
    }

    float* part = g_part + ((size_t)(b * NJC + jc)) * TLEN + t8;
    *reinterpret_cast<float4*>(part)     = make_float4(a[0], a[1], a[2], a[3]);
    *reinterpret_cast<float4*>(part + 4) = make_float4(a[4], a[5], a[6], a[7]);
}

// ---------------------------------------------------------------------------
// Kernel 4: out[b][t] = sum_{jc} g_part[b][jc][t]
// ---------------------------------------------------------------------------
__global__ __launch_bounds__(256) void combine_kernel(float* __restrict__ out)
{
    const int idx = blockIdx.x * 256 + threadIdx.x;   // 0..32767
    const int b   = idx >> 9;
    const int t4  = (idx & 511) * 4;

    const float* p = g_part + ((size_t)b * NJC) * TLEN + t4;
    float4 s = make_float4(0.f, 0.f, 0.f, 0.f);
    #pragma unroll
    for (int jc = 0; jc < NJC; ++jc) {
        const float4 v = *reinterpret_cast<const float4*>(p + (size_t)jc * TLEN);
        s.x += v.x; s.y += v.y; s.z += v.z; s.w += v.w;
    }
    *reinterpret_cast<float4*>(out + (size_t)b * TLEN + t4) = s;
}

// ---------------------------------------------------------------------------
extern "C" void kernel_launch(void* const* d_in, const int* in_sizes, int n_in,
                              void* d_out, int out_size)
{
    const float* question = (const float*)d_in[0];
    const float* context  = (const float*)d_in[1];
    const int*   qlen     = (const int*)d_in[2];
    const int*   clen     = (const int*)d_in[3];
    const float* weight   = (const float*)d_in[4];
    float* out = (float*)d_out;

    cudaFuncSetAttribute(gemm_kernel, cudaFuncAttributeMaxDynamicSharedMemorySize, SM_TOTAL);

    prep_kernel<<<BATCH * JLEN, 128>>>(question, weight);

    dim3 g1(TLEN / TT, BATCH);              // 16 x 64
    gemm_kernel<<<g1, 256, SM_TOTAL>>>(context, qlen, clen);

    cstats_kernel<<<BATCH * JLEN / 256, 256>>>(qlen, clen);   // 32 x 256

    dim3 g3(NJC, BATCH);                    // 8 x 64
    out_part_kernel<<<g3, 256>>>(qlen, clen);

    combine_kernel<<<BATCH * TLEN / 1024, 256>>>(out);        // 128 x 256
}

// round 13
// speedup vs baseline: 1.1719x; 1.0161x over previous
#include <cuda_runtime.h>
#include <cuda_bf16.h>
#include <cuda_fp16.h>
#include <cstdint>

#define BATCH 64
#define TLEN 2048
#define JLEN 128
#define DDIM 512

#define TT   128              // t per CTA (N tile)
#define KC   64               // k per chunk (64 bf16 = 128B row, SW128 atom)
#define NTILE (TLEN / TT)     // 16 t-tiles

// smem offsets (bytes) within 64KB dynamic smem
#define A_HI 0
#define A_LO 16384
#define B_HI 32768
#define B_LO 49152
#define SM_TOTAL 65536

#define NJC 16                // j-chunks in out pass
#define JCW (JLEN / NJC)      // 8 j per chunk

#define SWZ128(off) ((off) ^ (((off) >> 3) & 0x70))

// Scratch
__device__ __half g_p[(size_t)BATCH * JLEN * TLEN];            // exp(sim - m_local), fp16
__device__ float g_m[(size_t)BATCH * JLEN * NTILE];            // per-tile local max
__device__ float g_s[(size_t)BATCH * JLEN * NTILE];            // per-tile local expsum
__device__ float g_factor[(size_t)BATCH * JLEN * NTILE];       // exp(m-M)/S
__device__ float g_part[(size_t)BATCH * NJC * TLEN];           // out partials
__device__ __nv_bfloat16 g_qhi[(size_t)BATCH * JLEN * DDIM];   // (question*w) hi
__device__ __nv_bfloat16 g_qlo[(size_t)BATCH * JLEN * DDIM];   // (question*w) lo

// ---------------------------------------------------------------------------
// helpers
// ---------------------------------------------------------------------------
__device__ __forceinline__ uint32_t smem_u32(const void* p) {
    uint32_t a;
    asm("{ .reg .u64 t; cvta.to.shared.u64 t, %1; cvt.u32.u64 %0, t; }" : "=r"(a) : "l"(p));
    return a;
}

#define LDSM_X4(R, ADDR) \
    asm volatile("ldmatrix.sync.aligned.m8n8.x4.shared.b16 {%0,%1,%2,%3}, [%4];" \
        : "=r"((R)[0]), "=r"((R)[1]), "=r"((R)[2]), "=r"((R)[3]) : "r"(ADDR))

#define CP_ASYNC16(dst, src) \
    asm volatile("cp.async.cg.shared.global [%0], [%1], 16;" :: "r"(dst), "l"(src))
#define CP_COMMIT() asm volatile("cp.async.commit_group;" ::: "memory")
#define CP_WAIT0()  asm volatile("cp.async.wait_group 0;" ::: "memory")

__device__ __forceinline__ void mma16816(float* d, const uint32_t* a, const uint32_t* b) {
    asm volatile(
        "mma.sync.aligned.m16n8k16.row.col.f32.bf16.bf16.f32 "
        "{%0,%1,%2,%3}, {%4,%5,%6,%7}, {%8,%9}, {%0,%1,%2,%3};"
        : "+f"(d[0]), "+f"(d[1]), "+f"(d[2]), "+f"(d[3])
        : "r"(a[0]), "r"(a[1]), "r"(a[2]), "r"(a[3]), "r"(b[0]), "r"(b[1]));
}

// pack bf16(lo), bf16(hi) -> u32 {low16=bf16(lo), high16=bf16(hi)}  (round-nearest)
__device__ __forceinline__ uint32_t cvt2bf(float lo, float hi) {
    uint32_t r;
    asm("cvt.rn.bf16x2.f32 %0, %1, %2;" : "=r"(r) : "f"(hi), "f"(lo));
    return r;
}

// split float4 -> packed bf16 hi pair (h01,h23) and lo (residual) pair (l01,l23)
__device__ __forceinline__ void split4(const float4 v, uint32_t& h01, uint32_t& h23,
                                       uint32_t& l01, uint32_t& l23) {
    h01 = cvt2bf(v.x, v.y);
    h23 = cvt2bf(v.z, v.w);
    const float f0 = __uint_as_float(h01 << 16);
    const float f1 = __uint_as_float(h01 & 0xffff0000u);
    const float f2 = __uint_as_float(h23 << 16);
    const float f3 = __uint_as_float(h23 & 0xffff0000u);
    l01 = cvt2bf(v.x - f0, v.y - f1);
    l23 = cvt2bf(v.z - f2, v.w - f3);
}

// ---------------------------------------------------------------------------
// Kernel 0: split (question * w) into bf16 hi/lo global scratch
// ---------------------------------------------------------------------------
__global__ __launch_bounds__(128) void prep_kernel(
    const float* __restrict__ question,
    const float* __restrict__ weight)
{
    const int row = blockIdx.x;            // b*128 + j
    const int k4  = threadIdx.x * 4;
    const float4 q = __ldg(reinterpret_cast<const float4*>(question + (size_t)row * DDIM + k4));
    const float4 w = __ldg(reinterpret_cast<const float4*>(weight + k4));
    float4 v = make_float4(q.x * w.x, q.y * w.y, q.z * w.z, q.w * w.w);
    uint32_t h01, h23, l01, l23;
    split4(v, h01, h23, l01, l23);
    *reinterpret_cast<uint2*>(g_qhi + (size_t)row * DDIM + k4) = make_uint2(h01, h23);
    *reinterpret_cast<uint2*>(g_qlo + (size_t)row * DDIM + k4) = make_uint2(l01, l23);
}

// ---------------------------------------------------------------------------
// Kernel 1: HMMA GEMM + fused local softmax epilogue. 2 CTAs/SM.
// ---------------------------------------------------------------------------
__global__ __launch_bounds__(256, 2) void gemm_kernel(
    const float* __restrict__ context,
    const int* __restrict__ qlen,
    const int* __restrict__ clen)
{
    extern __shared__ __align__(1024) char smem[];
    const int b  = blockIdx.y;
    const int t0 = blockIdx.x * TT;
    const int cl = clen[b];
    if (t0 >= cl) return;
    const int ql = qlen[b];
    const int qlr = (ql + 15) & ~15;

    const uint32_t sb = smem_u32(smem);
    const int tid  = threadIdx.x;
    const int lane = tid & 31;
    const int wid  = tid >> 5;

    const int jbase = (wid & 1) << 6;
    const int tbase = (wid >> 1) << 5;

    const int r    = lane & 7;
    const int quad = lane >> 3;

    float acc[4][4][4];
    #pragma unroll
    for (int mt = 0; mt < 4; ++mt)
        #pragma unroll
        for (int nt = 0; nt < 4; ++nt)
            #pragma unroll
            for (int i = 0; i < 4; ++i) acc[mt][nt][i] = 0.0f;

    for (int kb = 0; kb < DDIM; kb += KC) {
        // ---- stage A via cp.async (bf16 hi/lo) : rows < qlr ----
        #pragma unroll
        for (int it = 0; it < 4; ++it) {
            const int idx = tid + it * 256;
            const int row = idx >> 3;
            const int u   = idx & 7;
            if (row < qlr) {
                const size_t src = ((size_t)(b * JLEN + row)) * DDIM + kb + u * 8;
                const uint32_t off = SWZ128((uint32_t)(row * 128 + u * 16));
                CP_ASYNC16(sb + A_HI + off, g_qhi + src);
                CP_ASYNC16(sb + A_LO + off, g_qlo + src);
            }
        }
        CP_COMMIT();

        // ---- stage B (context fp32 -> bf16 split) ----
        #pragma unroll
        for (int it = 0; it < 8; ++it) {
            const int idx = tid + it * 256;
            const int row = idx >> 4;
            const int u   = idx & 15;
            const float4 c = __ldg(reinterpret_cast<const float4*>(
                context + ((size_t)(b * TLEN + t0 + row)) * DDIM + kb + u * 4));
            uint32_t h01, h23, l01, l23;
            split4(c, h01, h23, l01, l23);
            const uint32_t off = SWZ128((uint32_t)(row * 128 + u * 8));
            *reinterpret_cast<uint2*>(smem + B_HI + off) = make_uint2(h01, h23);
            *reinterpret_cast<uint2*>(smem + B_LO + off) = make_uint2(l01, l23);
        }
        CP_WAIT0();
        __syncthreads();

        // ---- compute: 4 k16-steps ----
        #pragma unroll
        for (int ks = 0; ks < 4; ++ks) {
            uint32_t bh[8], bl[8];
            #pragma unroll
            for (int p = 0; p < 2; ++p) {
                const int tile  = p * 2 + (quad >> 1);
                const int khalf = quad & 1;
                const int rowt  = tbase + tile * 8 + r;
                const uint32_t off = SWZ128((uint32_t)(rowt * 128 + ks * 32 + khalf * 16));
                LDSM_X4(bh + p * 4, sb + B_HI + off);
                LDSM_X4(bl + p * 4, sb + B_LO + off);
            }
            #pragma unroll
            for (int mt = 0; mt < 4; ++mt) {
                if (jbase + mt * 16 < ql) {
                    const int rowa = jbase + mt * 16 + ((quad & 1) << 3) + r;
                    const uint32_t off = SWZ128((uint32_t)(rowa * 128 + ks * 32 + ((quad >> 1) << 4)));
                    uint32_t ah[4], al[4];
                    LDSM_X4(ah, sb + A_HI + off);
                    LDSM_X4(al, sb + A_LO + off);
                    #pragma unroll
                    for (int nt = 0; nt < 4; ++nt) {
                        mma16816(acc[mt][nt], ah, bh + nt * 2);
                        mma16816(acc[mt][nt], al, bh + nt * 2);
                        mma16816(acc[mt][nt], ah, bl + nt * 2);
                    }
                }
            }
        }
        __syncthreads();
    }

    // =================== fused softmax epilogue ===================
    float* red  = reinterpret_cast<float*>(smem);          // 512 floats
    float* mfin = red + 512;                               // 128 floats

    const int g   = lane >> 2;
    const int tig = lane & 3;
    const int tw  = wid >> 1;
    const float NEG = -3.4028235e38f;

    // ---- pass 1: local max per j-row over this tile (masked by cl) ----
    float mrow[8];
    #pragma unroll
    for (int mt = 0; mt < 4; ++mt) {
        #pragma unroll
        for (int h = 0; h < 2; ++h) {
            float mm = NEG;
            #pragma unroll
            for (int nt = 0; nt < 4; ++nt) {
                const int tg = t0 + tbase + nt * 8 + tig * 2;
                const float v0 = (tg     < cl) ? acc[mt][nt][h * 2 + 0] : NEG;
                const float v1 = (tg + 1 < cl) ? acc[mt][nt][h * 2 + 1] : NEG;
                mm = fmaxf(mm, fmaxf(v0, v1));
            }
            mrow[mt * 2 + h] = mm;
        }
    }
    #pragma unroll
    for (int i = 0; i < 8; ++i) {
        mrow[i] = fmaxf(mrow[i], __shfl_xor_sync(0xffffffffu, mrow[i], 1));
        mrow[i] = fmaxf(mrow[i], __shfl_xor_sync(0xffffffffu, mrow[i], 2));
    }
    if (tig == 0) {
        #pragma unroll
        for (int mt = 0; mt < 4; ++mt)
            #pragma unroll
            for (int h = 0; h < 2; ++h) {
                const int row = jbase + mt * 16 + h * 8 + g;
                red[tw * 128 + row] = mrow[mt * 2 + h];
            }
    }
    __syncthreads();
    if (tid < 128)
        mfin[tid] = fmaxf(fmaxf(red[tid], red[128 + tid]),
                          fmaxf(red[256 + tid], red[384 + tid]));
    __syncthreads();

    // ---- pass 2: exp, store p (fp16), per-row sums ----
    float srow[8];
    #pragma unroll
    for (int mt = 0; mt < 4; ++mt) {
        const bool live = (jbase + mt * 16 < ql);
        #pragma unroll
        for (int h = 0; h < 2; ++h) {
            const int row = jbase + mt * 16 + h * 8 + g;
            float s = 0.0f;
            if (live) {
                const float mref = mfin[row];
                __half* prow = g_p + ((size_t)(b * JLEN + row)) * TLEN;
                #pragma unroll
                for (int nt = 0; nt < 4; ++nt) {
                    const int tg = t0 + tbase + nt * 8 + tig * 2;
                    const float e0 = (tg     < cl) ? __expf(acc[mt][nt][h * 2 + 0] - mref) : 0.0f;
                    const float e1 = (tg + 1 < cl) ? __expf(acc[mt][nt][h * 2 + 1] - mref) : 0.0f;
                    s += e0 + e1;
                    *reinterpret_cast<__half2*>(prow + tg) = __floats2half2_rn(e0, e1);
                }
            }
            srow[mt * 2 + h] = s;
        }
    }
    #pragma unroll
    for (int i = 0; i < 8; ++i) {
        srow[i] += __shfl_xor_sync(0xffffffffu, srow[i], 1);
        srow[i] += __shfl_xor_sync(0xffffffffu, srow[i], 2);
    }
    __syncthreads();
    if (tig == 0) {
        #pragma unroll
        for (int mt = 0; mt < 4; ++mt)
            #pragma unroll
            for (int h = 0; h < 2; ++h) {
                const int row = jbase + mt * 16 + h * 8 + g;
                red[tw * 128 + row] = srow[mt * 2 + h];
            }
    }
    __syncthreads();
    if (tid < 128) {
        const float S = red[tid] + red[128 + tid] + red[256 + tid] + red[384 + tid];
        const int tile = t0 >> 7;
        g_m[((size_t)(b * JLEN) + tid) * NTILE + tile] = mfin[tid];
        g_s[((size_t)(b * JLEN) + tid) * NTILE + tile] = S;
    }
}

// ---------------------------------------------------------------------------
// Kernel 2: combine tile stats -> factor[b][j][tile] = exp(m-M)/S_global
// ---------------------------------------------------------------------------
__global__ __launch_bounds__(256) void cstats_kernel(
    const int* __restrict__ qlen,
    const int* __restrict__ clen)
{
    const int idx = blockIdx.x * 256 + threadIdx.x;   // b*128+j
    const int b = idx >> 7;
    const int j = idx & 127;
    const int ql = qlen[b];
    const int cl = clen[b];
    const int ntl = (cl + TT - 1) / TT;

    float f[NTILE];
    if (j < ql) {
        float mv[NTILE];
        float M = -3.4028235e38f;
        for (int k = 0; k < ntl; ++k) {
            mv[k] = g_m[(size_t)idx * NTILE + k];
            M = fmaxf(M, mv[k]);
        }
        float S = 0.0f;
        for (int k = 0; k < ntl; ++k) {
            mv[k] = __expf(mv[k] - M);
            S += g_s[(size_t)idx * NTILE + k] * mv[k];
        }
        const float inv = 1.0f / S;
        #pragma unroll
        for (int k = 0; k < NTILE; ++k)
            f[k] = (k < ntl) ? mv[k] * inv : 0.0f;
    } else {
        #pragma unroll
        for (int k = 0; k < NTILE; ++k) f[k] = 0.0f;
    }

    float* dst = g_factor + (size_t)idx * NTILE;
    #pragma unroll
    for (int q = 0; q < 4; ++q)
        *reinterpret_cast<float4*>(dst + q * 4) =
            make_float4(f[q * 4 + 0], f[q * 4 + 1], f[q * 4 + 2], f[q * 4 + 3]);
}

// ---------------------------------------------------------------------------
// Kernel 3: partial out over a j-chunk of 8.
// g_part[b][jc][t] = sum_{j in chunk} p[j][t] * factor[j][tile(t)]
// ---------------------------------------------------------------------------
__global__ __launch_bounds__(256) void out_part_kernel(
    const int* __restrict__ qlen,
    const int* __restrict__ clen)
{
    const int b  = blockIdx.y;
    const int jc = blockIdx.x;
    const int ql = qlen[b];
    const int cl = clen[b];
    const int j0 = jc * JCW;
    const int t8 = threadIdx.x * 8;

    __shared__ float sf[JCW][NTILE];
    if (threadIdx.x < JCW * NTILE) {
        const int jj = threadIdx.x >> 4;
        const int k  = threadIdx.x & 15;
        sf[jj][k] = g_factor[((size_t)(b * JLEN + j0 + jj)) * NTILE + k];
    }
    __syncthreads();

    float a[8];
    #pragma unroll
    for (int i = 0; i < 8; ++i) a[i] = 0.0f;

    if (j0 < ql && t8 < cl) {
        const int tile = t8 >> 7;
        const int nj = min(JCW, ql - j0);
        const __half* base = g_p + ((size_t)(b * JLEN + j0)) * TLEN + t8;
        for (int jj = 0; jj < nj; ++jj) {
            const uint4 u = *reinterpret_cast<const uint4*>(base + (size_t)jj * TLEN);
            const float dj = sf[jj][tile];
            const __half2* h = reinterpret_cast<const __half2*>(&u);
            #pragma unroll
            for (int q = 0; q < 4; ++q) {
                const float2 fv = __half22float2(h[q]);
                a[q * 2 + 0] += fv.x * dj;
                a[q * 2 + 1] += fv.y * dj;
            }
        }
    }

    float* part = g_part + ((size_t)(b * NJC + jc)) * TLEN + t8;
    *reinterpret_cast<float4*>(part)     = make_float4(a[0], a[1], a[2], a[3]);
    *reinterpret_cast<float4*>(part + 4) = make_float4(a[4], a[5], a[6], a[7]);
}

// ---------------------------------------------------------------------------
// Kernel 4: out[b][t] = sum_{jc} g_part[b][jc][t]
// ---------------------------------------------------------------------------
__global__ __launch_bounds__(256) void combine_kernel(float* __restrict__ out)
{
    const int idx = blockIdx.x * 256 + threadIdx.x;
    const int b   = idx >> 9;
    const int t4  = (idx & 511) * 4;

    const float* p = g_part + ((size_t)b * NJC) * TLEN + t4;
    float4 s = make_float4(0.f, 0.f, 0.f, 0.f);
    #pragma unroll
    for (int jc = 0; jc < NJC; ++jc) {
        const float4 v = *reinterpret_cast<const float4*>(p + (size_t)jc * TLEN);
        s.x += v.x; s.y += v.y; s.z += v.z; s.w += v.w;
    }
    *reinterpret_cast<float4*>(out + (size_t)b * TLEN + t4) = s;
}

// ---------------------------------------------------------------------------
extern "C" void kernel_launch(void* const* d_in, const int* in_sizes, int n_in,
                              void* d_out, int out_size)
{
    const float* question = (const float*)d_in[0];
    const float* context  = (const float*)d_in[1];
    const int*   qlen     = (const int*)d_in[2];
    const int*   clen     = (const int*)d_in[3];
    const float* weight   = (const float*)d_in[4];
    float* out = (float*)d_out;

    cudaFuncSetAttribute(gemm_kernel, cudaFuncAttributeMaxDynamicSharedMemorySize, SM_TOTAL);

    prep_kernel<<<BATCH * JLEN, 128>>>(question, weight);

    dim3 g1(TLEN / TT, BATCH);              // 16 x 64
    gemm_kernel<<<g1, 256, SM_TOTAL>>>(context, qlen, clen);

    cstats_kernel<<<BATCH * JLEN / 256, 256>>>(qlen, clen);   // 32 x 256

    dim3 g3(NJC, BATCH);                    // 16 x 64
    out_part_kernel<<<g3, 256>>>(qlen, clen);

    combine_kernel<<<BATCH * TLEN / 1024, 256>>>(out);        // 128 x 256
}

// round 14
// speedup vs baseline: 1.2104x; 1.0329x over previous
#include <cuda_runtime.h>
#include <cuda_bf16.h>
#include <cuda_fp16.h>
#include <cstdint>

#define BATCH 64
#define TLEN 2048
#define JLEN 128
#define DDIM 512

#define TT   128              // t per CTA (N tile)
#define KC   32               // k per pipeline stage (half a 128B SW128 row)
#define NSTAGE (DDIM / KC)    // 16 stages
#define NTILE (TLEN / TT)     // 16 t-tiles

// smem offsets (bytes) within 64KB dynamic smem
// each region: 128 rows x 128B; stage parity selects 64B half of each row
#define A_HI 0
#define A_LO 16384
#define B_HI 32768
#define B_LO 49152
#define SM_TOTAL 65536

#define NJC 16                // j-chunks in out pass
#define JCW (JLEN / NJC)      // 8 j per chunk

#define SWZ128(off) ((off) ^ (((off) >> 3) & 0x70))

// Scratch
__device__ __half g_p[(size_t)BATCH * JLEN * TLEN];            // exp(sim - m_local), fp16
__device__ float g_m[(size_t)BATCH * JLEN * NTILE];            // per-tile local max
__device__ float g_s[(size_t)BATCH * JLEN * NTILE];            // per-tile local expsum
__device__ float g_factor[(size_t)BATCH * JLEN * NTILE];       // exp(m-M)/S
__device__ float g_part[(size_t)BATCH * NJC * TLEN];           // out partials
__device__ __nv_bfloat16 g_qhi[(size_t)BATCH * JLEN * DDIM];   // (question*w) hi
__device__ __nv_bfloat16 g_qlo[(size_t)BATCH * JLEN * DDIM];   // (question*w) lo

// ---------------------------------------------------------------------------
// helpers
// ---------------------------------------------------------------------------
__device__ __forceinline__ uint32_t smem_u32(const void* p) {
    uint32_t a;
    asm("{ .reg .u64 t; cvta.to.shared.u64 t, %1; cvt.u32.u64 %0, t; }" : "=r"(a) : "l"(p));
    return a;
}

#define LDSM_X4(R, ADDR) \
    asm volatile("ldmatrix.sync.aligned.m8n8.x4.shared.b16 {%0,%1,%2,%3}, [%4];" \
        : "=r"((R)[0]), "=r"((R)[1]), "=r"((R)[2]), "=r"((R)[3]) : "r"(ADDR))

#define CP_ASYNC16(dst, src) \
    asm volatile("cp.async.cg.shared.global [%0], [%1], 16;" :: "r"(dst), "l"(src))
#define CP_COMMIT() asm volatile("cp.async.commit_group;" ::: "memory")
#define CP_WAIT0()  asm volatile("cp.async.wait_group 0;" ::: "memory")

__device__ __forceinline__ void mma16816(float* d, const uint32_t* a, const uint32_t* b) {
    asm volatile(
        "mma.sync.aligned.m16n8k16.row.col.f32.bf16.bf16.f32 "
        "{%0,%1,%2,%3}, {%4,%5,%6,%7}, {%8,%9}, {%0,%1,%2,%3};"
        : "+f"(d[0]), "+f"(d[1]), "+f"(d[2]), "+f"(d[3])
        : "r"(a[0]), "r"(a[1]), "r"(a[2]), "r"(a[3]), "r"(b[0]), "r"(b[1]));
}

// pack bf16(lo), bf16(hi) -> u32 {low16=bf16(lo), high16=bf16(hi)}  (round-nearest)
__device__ __forceinline__ uint32_t cvt2bf(float lo, float hi) {
    uint32_t r;
    asm("cvt.rn.bf16x2.f32 %0, %1, %2;" : "=r"(r) : "f"(hi), "f"(lo));
    return r;
}

// split float4 -> packed bf16 hi pair (h01,h23) and lo (residual) pair (l01,l23)
__device__ __forceinline__ void split4(const float4 v, uint32_t& h01, uint32_t& h23,
                                       uint32_t& l01, uint32_t& l23) {
    h01 = cvt2bf(v.x, v.y);
    h23 = cvt2bf(v.z, v.w);
    const float f0 = __uint_as_float(h01 << 16);
    const float f1 = __uint_as_float(h01 & 0xffff0000u);
    const float f2 = __uint_as_float(h23 << 16);
    const float f3 = __uint_as_float(h23 & 0xffff0000u);
    l01 = cvt2bf(v.x - f0, v.y - f1);
    l23 = cvt2bf(v.z - f2, v.w - f3);
}

// ---------------------------------------------------------------------------
// Kernel 0: split (question * w) into bf16 hi/lo global scratch
// ---------------------------------------------------------------------------
__global__ __launch_bounds__(128) void prep_kernel(
    const float* __restrict__ question,
    const float* __restrict__ weight)
{
    const int row = blockIdx.x;            // b*128 + j
    const int k4  = threadIdx.x * 4;
    const float4 q = __ldg(reinterpret_cast<const float4*>(question + (size_t)row * DDIM + k4));
    const float4 w = __ldg(reinterpret_cast<const float4*>(weight + k4));
    float4 v = make_float4(q.x * w.x, q.y * w.y, q.z * w.z, q.w * w.w);
    uint32_t h01, h23, l01, l23;
    split4(v, h01, h23, l01, l23);
    *reinterpret_cast<uint2*>(g_qhi + (size_t)row * DDIM + k4) = make_uint2(h01, h23);
    *reinterpret_cast<uint2*>(g_qlo + (size_t)row * DDIM + k4) = make_uint2(l01, l23);
}

// ---------------------------------------------------------------------------
// stage helpers for gemm pipeline (stage s covers k = [s*KC, s*KC+KC))
// smem half-row base (bytes within a 128B row) = (s & 1) * 64
// ---------------------------------------------------------------------------
__device__ __forceinline__ void stage_a_cpasync(
    uint32_t sb, int b, int s, int qlr, int tid)
{
    const int kbase = (s & 1) << 6;      // 0 or 64 bytes
    const int kg    = s * KC;
    #pragma unroll
    for (int it = 0; it < 2; ++it) {
        const int idx = tid + it * 256;           // 0..511
        const int row = idx >> 2;                 // 0..127
        const int u   = idx & 3;                  // 16B unit
        if (row < qlr) {
            const size_t src = ((size_t)(b * JLEN + row)) * DDIM + kg + u * 8;
            const uint32_t off = SWZ128((uint32_t)(row * 128 + kbase + u * 16));
            CP_ASYNC16(sb + A_HI + off, g_qhi + src);
            CP_ASYNC16(sb + A_LO + off, g_qlo + src);
        }
    }
}

// ---------------------------------------------------------------------------
// Kernel 1: HMMA GEMM + fused softmax epilogue. 2 CTAs/SM.
// 16-stage pipeline: stage s+1 staging overlaps stage s MMAs (half-row ping-pong).
// ---------------------------------------------------------------------------
__global__ __launch_bounds__(256, 2) void gemm_kernel(
    const float* __restrict__ context,
    const int* __restrict__ qlen,
    const int* __restrict__ clen)
{
    extern __shared__ __align__(1024) char smem[];
    const int b  = blockIdx.y;
    const int t0 = blockIdx.x * TT;
    const int cl = clen[b];
    if (t0 >= cl) return;
    const int ql = qlen[b];
    const int qlr = (ql + 15) & ~15;

    const uint32_t sb = smem_u32(smem);
    const int tid  = threadIdx.x;
    const int lane = tid & 31;
    const int wid  = tid >> 5;

    const int jbase = (wid & 1) << 6;
    const int tbase = (wid >> 1) << 5;

    const int r    = lane & 7;
    const int quad = lane >> 3;

    float acc[4][4][4];
    #pragma unroll
    for (int mt = 0; mt < 4; ++mt)
        #pragma unroll
        for (int nt = 0; nt < 4; ++nt)
            #pragma unroll
            for (int i = 0; i < 4; ++i) acc[mt][nt][i] = 0.0f;

    // B staging indices (4 float4 per thread per stage: 128 rows x 8 units)
    const int brow0 = tid >> 3;          // rows for it=0,1 base (idx>>3)
    // ---- prologue: stage 0 ----
    {
        stage_a_cpasync(sb, b, 0, qlr, tid);
        #pragma unroll
        for (int it = 0; it < 4; ++it) {
            const int idx = tid + it * 256;       // 0..1023
            const int row = idx >> 3;
            const int u   = idx & 7;
            const float4 c = __ldg(reinterpret_cast<const float4*>(
                context + ((size_t)(b * TLEN + t0 + row)) * DDIM + u * 4));
            uint32_t h01, h23, l01, l23;
            split4(c, h01, h23, l01, l23);
            const uint32_t off = SWZ128((uint32_t)(row * 128 + u * 8));
            *reinterpret_cast<uint2*>(smem + B_HI + off) = make_uint2(h01, h23);
            *reinterpret_cast<uint2*>(smem + B_LO + off) = make_uint2(l01, l23);
        }
        CP_COMMIT();
        CP_WAIT0();
        __syncthreads();
    }

    for (int s = 0; s < NSTAGE; ++s) {
        const int kbase = (s & 1) << 6;       // smem byte base of current stage
        const bool more = (s + 1 < NSTAGE);

        // ---- issue next-stage loads first (A cp.async + B LDG) ----
        float4 c0, c1, c2, c3;
        if (more) {
            stage_a_cpasync(sb, b, s + 1, qlr, tid);
            CP_COMMIT();
            const int kg = (s + 1) * KC;
            const float* cb = context + (size_t)(b * TLEN + t0) * DDIM + kg;
            const int row0 = tid >> 3, u0 = tid & 7;
            const int row1 = (tid + 256) >> 3, u1 = tid & 7;
            const int row2 = (tid + 512) >> 3, u2 = tid & 7;
            const int row3 = (tid + 768) >> 3, u3 = tid & 7;
            c0 = __ldg(reinterpret_cast<const float4*>(cb + (size_t)row0 * DDIM + u0 * 4));
            c1 = __ldg(reinterpret_cast<const float4*>(cb + (size_t)row1 * DDIM + u1 * 4));
            c2 = __ldg(reinterpret_cast<const float4*>(cb + (size_t)row2 * DDIM + u2 * 4));
            c3 = __ldg(reinterpret_cast<const float4*>(cb + (size_t)row3 * DDIM + u3 * 4));
        }

        // ---- MMAs for current stage (2 k16-steps) ----
        #pragma unroll
        for (int ks = 0; ks < 2; ++ks) {
            uint32_t bh[8], bl[8];
            #pragma unroll
            for (int p = 0; p < 2; ++p) {
                const int tile  = p * 2 + (quad >> 1);
                const int khalf = quad & 1;
                const int rowt  = tbase + tile * 8 + r;
                const uint32_t off = SWZ128((uint32_t)(rowt * 128 + kbase + ks * 32 + khalf * 16));
                LDSM_X4(bh + p * 4, sb + B_HI + off);
                LDSM_X4(bl + p * 4, sb + B_LO + off);
            }
            #pragma unroll
            for (int mt = 0; mt < 4; ++mt) {
                if (jbase + mt * 16 < ql) {
                    const int rowa = jbase + mt * 16 + ((quad & 1) << 3) + r;
                    const uint32_t off = SWZ128((uint32_t)(rowa * 128 + kbase + ks * 32 + ((quad >> 1) << 4)));
                    uint32_t ah[4], al[4];
                    LDSM_X4(ah, sb + A_HI + off);
                    LDSM_X4(al, sb + A_LO + off);
                    #pragma unroll
                    for (int nt = 0; nt < 4; ++nt) {
                        mma16816(acc[mt][nt], ah, bh + nt * 2);
                        mma16816(acc[mt][nt], al, bh + nt * 2);
                        mma16816(acc[mt][nt], ah, bl + nt * 2);
                    }
                }
            }
        }

        // ---- convert + store next-stage B into the other half-row ----
        if (more) {
            const uint32_t nkb = ((s + 1) & 1) << 6;
            uint32_t h01, h23, l01, l23;
            const int rows[4] = { tid >> 3, (tid + 256) >> 3, (tid + 512) >> 3, (tid + 768) >> 3 };
            const int u = tid & 7;
            split4(c0, h01, h23, l01, l23);
            uint32_t off = SWZ128((uint32_t)(rows[0] * 128 + nkb + u * 8));
            *reinterpret_cast<uint2*>(smem + B_HI + off) = make_uint2(h01, h23);
            *reinterpret_cast<uint2*>(smem + B_LO + off) = make_uint2(l01, l23);
            split4(c1, h01, h23, l01, l23);
            off = SWZ128((uint32_t)(rows[1] * 128 + nkb + u * 8));
            *reinterpret_cast<uint2*>(smem + B_HI + off) = make_uint2(h01, h23);
            *reinterpret_cast<uint2*>(smem + B_LO + off) = make_uint2(l01, l23);
            split4(c2, h01, h23, l01, l23);
            off = SWZ128((uint32_t)(rows[2] * 128 + nkb + u * 8));
            *reinterpret_cast<uint2*>(smem + B_HI + off) = make_uint2(h01, h23);
            *reinterpret_cast<uint2*>(smem + B_LO + off) = make_uint2(l01, l23);
            split4(c3, h01, h23, l01, l23);
            off = SWZ128((uint32_t)(rows[3] * 128 + nkb + u * 8));
            *reinterpret_cast<uint2*>(smem + B_HI + off) = make_uint2(h01, h23);
            *reinterpret_cast<uint2*>(smem + B_LO + off) = make_uint2(l01, l23);
            CP_WAIT0();
        }
        __syncthreads();
    }

    // =================== fused softmax epilogue ===================
    float* red  = reinterpret_cast<float*>(smem);          // 512 floats
    float* mfin = red + 512;                               // 128 floats

    const int g   = lane >> 2;
    const int tig = lane & 3;
    const int tw  = wid >> 1;
    const float NEG = -3.4028235e38f;

    float mrow[8];
    #pragma unroll
    for (int mt = 0; mt < 4; ++mt) {
        #pragma unroll
        for (int h = 0; h < 2; ++h) {
            float mm = NEG;
            #pragma unroll
            for (int nt = 0; nt < 4; ++nt) {
                const int tg = t0 + tbase + nt * 8 + tig * 2;
                const float v0 = (tg     < cl) ? acc[mt][nt][h * 2 + 0] : NEG;
                const float v1 = (tg + 1 < cl) ? acc[mt][nt][h * 2 + 1] : NEG;
                mm = fmaxf(mm, fmaxf(v0, v1));
            }
            mrow[mt * 2 + h] = mm;
        }
    }
    #pragma unroll
    for (int i = 0; i < 8; ++i) {
        mrow[i] = fmaxf(mrow[i], __shfl_xor_sync(0xffffffffu, mrow[i], 1));
        mrow[i] = fmaxf(mrow[i], __shfl_xor_sync(0xffffffffu, mrow[i], 2));
    }
    if (tig == 0) {
        #pragma unroll
        for (int mt = 0; mt < 4; ++mt)
            #pragma unroll
            for (int h = 0; h < 2; ++h) {
                const int row = jbase + mt * 16 + h * 8 + g;
                red[tw * 128 + row] = mrow[mt * 2 + h];
            }
    }
    __syncthreads();
    if (tid < 128)
        mfin[tid] = fmaxf(fmaxf(red[tid], red[128 + tid]),
                          fmaxf(red[256 + tid], red[384 + tid]));
    __syncthreads();

    float srow[8];
    #pragma unroll
    for (int mt = 0; mt < 4; ++mt) {
        const bool live = (jbase + mt * 16 < ql);
        #pragma unroll
        for (int h = 0; h < 2; ++h) {
            const int row = jbase + mt * 16 + h * 8 + g;
            float s = 0.0f;
            if (live) {
                const float mref = mfin[row];
                __half* prow = g_p + ((size_t)(b * JLEN + row)) * TLEN;
                #pragma unroll
                for (int nt = 0; nt < 4; ++nt) {
                    const int tg = t0 + tbase + nt * 8 + tig * 2;
                    const float e0 = (tg     < cl) ? __expf(acc[mt][nt][h * 2 + 0] - mref) : 0.0f;
                    const float e1 = (tg + 1 < cl) ? __expf(acc[mt][nt][h * 2 + 1] - mref) : 0.0f;
                    s += e0 + e1;
                    *reinterpret_cast<__half2*>(prow + tg) = __floats2half2_rn(e0, e1);
                }
            }
            srow[mt * 2 + h] = s;
        }
    }
    #pragma unroll
    for (int i = 0; i < 8; ++i) {
        srow[i] += __shfl_xor_sync(0xffffffffu, srow[i], 1);
        srow[i] += __shfl_xor_sync(0xffffffffu, srow[i], 2);
    }
    __syncthreads();
    if (tig == 0) {
        #pragma unroll
        for (int mt = 0; mt < 4; ++mt)
            #pragma unroll
            for (int h = 0; h < 2; ++h) {
                const int row = jbase + mt * 16 + h * 8 + g;
                red[tw * 128 + row] = srow[mt * 2 + h];
            }
    }
    __syncthreads();
    if (tid < 128) {
        const float S = red[tid] + red[128 + tid] + red[256 + tid] + red[384 + tid];
        const int tile = t0 >> 7;
        g_m[((size_t)(b * JLEN) + tid) * NTILE + tile] = mfin[tid];
        g_s[((size_t)(b * JLEN) + tid) * NTILE + tile] = S;
    }
}

// ---------------------------------------------------------------------------
// Kernel 2: combine tile stats -> factor[b][j][tile] = exp(m-M)/S_global
// ---------------------------------------------------------------------------
__global__ __launch_bounds__(256) void cstats_kernel(
    const int* __restrict__ qlen,
    const int* __restrict__ clen)
{
    const int idx = blockIdx.x * 256 + threadIdx.x;   // b*128+j
    const int b = idx >> 7;
    const int j = idx & 127;
    const int ql = qlen[b];
    const int cl = clen[b];
    const int ntl = (cl + TT - 1) / TT;

    float f[NTILE];
    if (j < ql) {
        float mv[NTILE];
        float M = -3.4028235e38f;
        for (int k = 0; k < ntl; ++k) {
            mv[k] = g_m[(size_t)idx * NTILE + k];
            M = fmaxf(M, mv[k]);
        }
        float S = 0.0f;
        for (int k = 0; k < ntl; ++k) {
            mv[k] = __expf(mv[k] - M);
            S += g_s[(size_t)idx * NTILE + k] * mv[k];
        }
        const float inv = 1.0f / S;
        #pragma unroll
        for (int k = 0; k < NTILE; ++k)
            f[k] = (k < ntl) ? mv[k] * inv : 0.0f;
    } else {
        #pragma unroll
        for (int k = 0; k < NTILE; ++k) f[k] = 0.0f;
    }

    float* dst = g_factor + (size_t)idx * NTILE;
    #pragma unroll
    for (int q = 0; q < 4; ++q)
        *reinterpret_cast<float4*>(dst + q * 4) =
            make_float4(f[q * 4 + 0], f[q * 4 + 1], f[q * 4 + 2], f[q * 4 + 3]);
}

// ---------------------------------------------------------------------------
// Kernel 3: partial out over a j-chunk of 8.
// ---------------------------------------------------------------------------
__global__ __launch_bounds__(256) void out_part_kernel(
    const int* __restrict__ qlen,
    const int* __restrict__ clen)
{
    const int b  = blockIdx.y;
    const int jc = blockIdx.x;
    const int ql = qlen[b];
    const int cl = clen[b];
    const int j0 = jc * JCW;
    const int t8 = threadIdx.x * 8;

    __shared__ float sf[JCW][NTILE];
    if (threadIdx.x < JCW * NTILE) {
        const int jj = threadIdx.x >> 4;
        const int k  = threadIdx.x & 15;
        sf[jj][k] = g_factor[((size_t)(b * JLEN + j0 + jj)) * NTILE + k];
    }
    __syncthreads();

    float a[8];
    #pragma unroll
    for (int i = 0; i < 8; ++i) a[i] = 0.0f;

    if (j0 < ql && t8 < cl) {
        const int tile = t8 >> 7;
        const int nj = min(JCW, ql - j0);
        const __half* base = g_p + ((size_t)(b * JLEN + j0)) * TLEN + t8;
        for (int jj = 0; jj < nj; ++jj) {
            const uint4 u = *reinterpret_cast<const uint4*>(base + (size_t)jj * TLEN);
            const float dj = sf[jj][tile];
            const __half2* h = reinterpret_cast<const __half2*>(&u);
            #pragma unroll
            for (int q = 0; q < 4; ++q) {
                const float2 fv = __half22float2(h[q]);
                a[q * 2 + 0] += fv.x * dj;
                a[q * 2 + 1] += fv.y * dj;
            }
        }
    }

    float* part = g_part + ((size_t)(b * NJC + jc)) * TLEN + t8;
    *reinterpret_cast<float4*>(part)     = make_float4(a[0], a[1], a[2], a[3]);
    *reinterpret_cast<float4*>(part + 4) = make_float4(a[4], a[5], a[6], a[7]);
}

// ---------------------------------------------------------------------------
// Kernel 4: out[b][t] = sum_{jc} g_part[b][jc][t]
// ---------------------------------------------------------------------------
__global__ __launch_bounds__(256) void combine_kernel(float* __restrict__ out)
{
    const int idx = blockIdx.x * 256 + threadIdx.x;
    const int b   = idx >> 9;
    const int t4  = (idx & 511) * 4;

    const float* p = g_part + ((size_t)b * NJC) * TLEN + t4;
    float4 s = make_float4(0.f, 0.f, 0.f, 0.f);
    #pragma unroll
    for (int jc = 0; jc < NJC; ++jc) {
        const float4 v = *reinterpret_cast<const float4*>(p + (size_t)jc * TLEN);
        s.x += v.x; s.y += v.y; s.z += v.z; s.w += v.w;
    }
    *reinterpret_cast<float4*>(out + (size_t)b * TLEN + t4) = s;
}

// ---------------------------------------------------------------------------
extern "C" void kernel_launch(void* const* d_in, const int* in_sizes, int n_in,
                              void* d_out, int out_size)
{
    const float* question = (const float*)d_in[0];
    const float* context  = (const float*)d_in[1];
    const int*   qlen     = (const int*)d_in[2];
    const int*   clen     = (const int*)d_in[3];
    const float* weight   = (const float*)d_in[4];
    float* out = (float*)d_out;

    cudaFuncSetAttribute(gemm_kernel, cudaFuncAttributeMaxDynamicSharedMemorySize, SM_TOTAL);

    prep_kernel<<<BATCH * JLEN, 128>>>(question, weight);

    dim3 g1(TLEN / TT, BATCH);              // 16 x 64
    gemm_kernel<<<g1, 256, SM_TOTAL>>>(context, qlen, clen);

    cstats_kernel<<<BATCH * JLEN / 256, 256>>>(qlen, clen);   // 32 x 256

    dim3 g3(NJC, BATCH);                    // 16 x 64
    out_part_kernel<<<g3, 256>>>(qlen, clen);

    combine_kernel<<<BATCH * TLEN / 1024, 256>>>(out);        // 128 x 256
}

// round 15
// speedup vs baseline: 1.3054x; 1.0785x over previous
#include <cuda_runtime.h>
#include <cuda_bf16.h>
#include <cuda_fp16.h>
#include <cstdint>

#define BATCH 64
#define TLEN 2048
#define JLEN 128
#define DDIM 512

#define TT   128              // t per CTA (N tile)
#define KC   32               // k per pipeline stage (half a 128B SW128 row)
#define NSTAGE (DDIM / KC)    // 16 stages
#define NTILE (TLEN / TT)     // 16 t-tiles

// smem offsets (bytes) within 64KB dynamic smem
#define A_HI 0
#define A_LO 16384
#define B_HI 32768
#define B_LO 49152
#define SM_TOTAL 65536

#define NJC 16                // j-chunks in out pass
#define JCW (JLEN / NJC)      // 8 j per chunk

#define SWZ128(off) ((off) ^ (((off) >> 3) & 0x70))

// Scratch
__device__ __half g_p[(size_t)BATCH * JLEN * TLEN];            // exp(sim - m_local), fp16
__device__ float g_m[(size_t)BATCH * JLEN * NTILE];            // per-tile local max
__device__ float g_s[(size_t)BATCH * JLEN * NTILE];            // per-tile local expsum
__device__ float g_part[(size_t)BATCH * NJC * TLEN];           // out partials
__device__ __nv_bfloat16 g_qhi[(size_t)BATCH * JLEN * DDIM];   // (question*w) hi
__device__ __nv_bfloat16 g_qlo[(size_t)BATCH * JLEN * DDIM];   // (question*w) lo

// ---------------------------------------------------------------------------
// helpers
// ---------------------------------------------------------------------------
__device__ __forceinline__ uint32_t smem_u32(const void* p) {
    uint32_t a;
    asm("{ .reg .u64 t; cvta.to.shared.u64 t, %1; cvt.u32.u64 %0, t; }" : "=r"(a) : "l"(p));
    return a;
}

#define LDSM_X4(R, ADDR) \
    asm volatile("ldmatrix.sync.aligned.m8n8.x4.shared.b16 {%0,%1,%2,%3}, [%4];" \
        : "=r"((R)[0]), "=r"((R)[1]), "=r"((R)[2]), "=r"((R)[3]) : "r"(ADDR))

#define CP_ASYNC16(dst, src) \
    asm volatile("cp.async.cg.shared.global [%0], [%1], 16;" :: "r"(dst), "l"(src))
#define CP_COMMIT() asm volatile("cp.async.commit_group;" ::: "memory")
#define CP_WAIT0()  asm volatile("cp.async.wait_group 0;" ::: "memory")

__device__ __forceinline__ void mma16816(float* d, const uint32_t* a, const uint32_t* b) {
    asm volatile(
        "mma.sync.aligned.m16n8k16.row.col.f32.bf16.bf16.f32 "
        "{%0,%1,%2,%3}, {%4,%5,%6,%7}, {%8,%9}, {%0,%1,%2,%3};"
        : "+f"(d[0]), "+f"(d[1]), "+f"(d[2]), "+f"(d[3])
        : "r"(a[0]), "r"(a[1]), "r"(a[2]), "r"(a[3]), "r"(b[0]), "r"(b[1]));
}

// pack bf16(lo), bf16(hi) -> u32 {low16=bf16(lo), high16=bf16(hi)}  (round-nearest)
__device__ __forceinline__ uint32_t cvt2bf(float lo, float hi) {
    uint32_t r;
    asm("cvt.rn.bf16x2.f32 %0, %1, %2;" : "=r"(r) : "f"(hi), "f"(lo));
    return r;
}

// split float4 -> packed bf16 hi pair (h01,h23) and lo (residual) pair (l01,l23)
__device__ __forceinline__ void split4(const float4 v, uint32_t& h01, uint32_t& h23,
                                       uint32_t& l01, uint32_t& l23) {
    h01 = cvt2bf(v.x, v.y);
    h23 = cvt2bf(v.z, v.w);
    const float f0 = __uint_as_float(h01 << 16);
    const float f1 = __uint_as_float(h01 & 0xffff0000u);
    const float f2 = __uint_as_float(h23 << 16);
    const float f3 = __uint_as_float(h23 & 0xffff0000u);
    l01 = cvt2bf(v.x - f0, v.y - f1);
    l23 = cvt2bf(v.z - f2, v.w - f3);
}

// ---------------------------------------------------------------------------
// Kernel 0: split (question * w) into bf16 hi/lo global scratch
// ---------------------------------------------------------------------------
__global__ __launch_bounds__(128) void prep_kernel(
    const float* __restrict__ question,
    const float* __restrict__ weight)
{
    const int row = blockIdx.x;            // b*128 + j
    const int k4  = threadIdx.x * 4;
    const float4 q = __ldg(reinterpret_cast<const float4*>(question + (size_t)row * DDIM + k4));
    const float4 w = __ldg(reinterpret_cast<const float4*>(weight + k4));
    float4 v = make_float4(q.x * w.x, q.y * w.y, q.z * w.z, q.w * w.w);
    uint32_t h01, h23, l01, l23;
    split4(v, h01, h23, l01, l23);
    *reinterpret_cast<uint2*>(g_qhi + (size_t)row * DDIM + k4) = make_uint2(h01, h23);
    *reinterpret_cast<uint2*>(g_qlo + (size_t)row * DDIM + k4) = make_uint2(l01, l23);
}

// ---------------------------------------------------------------------------
// stage helpers for gemm pipeline (stage s covers k = [s*KC, s*KC+KC))
// ---------------------------------------------------------------------------
__device__ __forceinline__ void stage_a_cpasync(
    uint32_t sb, int b, int s, int qlr, int tid)
{
    const int kbase = (s & 1) << 6;      // 0 or 64 bytes
    const int kg    = s * KC;
    #pragma unroll
    for (int it = 0; it < 2; ++it) {
        const int idx = tid + it * 256;           // 0..511
        const int row = idx >> 2;                 // 0..127
        const int u   = idx & 3;                  // 16B unit
        if (row < qlr) {
            const size_t src = ((size_t)(b * JLEN + row)) * DDIM + kg + u * 8;
            const uint32_t off = SWZ128((uint32_t)(row * 128 + kbase + u * 16));
            CP_ASYNC16(sb + A_HI + off, g_qhi + src);
            CP_ASYNC16(sb + A_LO + off, g_qlo + src);
        }
    }
}

// ---------------------------------------------------------------------------
// Kernel 1: HMMA GEMM + fused softmax epilogue. No reg cap (avoid spills).
// 16-stage pipeline: stage s+1 staging overlaps stage s MMAs (half-row ping-pong).
// ---------------------------------------------------------------------------
__global__ __launch_bounds__(256) void gemm_kernel(
    const float* __restrict__ context,
    const int* __restrict__ qlen,
    const int* __restrict__ clen)
{
    extern __shared__ __align__(1024) char smem[];
    const int b  = blockIdx.y;
    const int t0 = blockIdx.x * TT;
    const int cl = clen[b];
    if (t0 >= cl) return;
    const int ql = qlen[b];
    const int qlr = (ql + 15) & ~15;

    const uint32_t sb = smem_u32(smem);
    const int tid  = threadIdx.x;
    const int lane = tid & 31;
    const int wid  = tid >> 5;

    const int jbase = (wid & 1) << 6;
    const int tbase = (wid >> 1) << 5;

    const int r    = lane & 7;
    const int quad = lane >> 3;

    float acc[4][4][4];
    #pragma unroll
    for (int mt = 0; mt < 4; ++mt)
        #pragma unroll
        for (int nt = 0; nt < 4; ++nt)
            #pragma unroll
            for (int i = 0; i < 4; ++i) acc[mt][nt][i] = 0.0f;

    // ---- prologue: stage 0 ----
    {
        stage_a_cpasync(sb, b, 0, qlr, tid);
        #pragma unroll
        for (int it = 0; it < 4; ++it) {
            const int idx = tid + it * 256;       // 0..1023
            const int row = idx >> 3;
            const int u   = idx & 7;
            const float4 c = __ldg(reinterpret_cast<const float4*>(
                context + ((size_t)(b * TLEN + t0 + row)) * DDIM + u * 4));
            uint32_t h01, h23, l01, l23;
            split4(c, h01, h23, l01, l23);
            const uint32_t off = SWZ128((uint32_t)(row * 128 + u * 8));
            *reinterpret_cast<uint2*>(smem + B_HI + off) = make_uint2(h01, h23);
            *reinterpret_cast<uint2*>(smem + B_LO + off) = make_uint2(l01, l23);
        }
        CP_COMMIT();
        CP_WAIT0();
        __syncthreads();
    }

    for (int s = 0; s < NSTAGE; ++s) {
        const int kbase = (s & 1) << 6;       // smem byte base of current stage
        const bool more = (s + 1 < NSTAGE);

        // ---- issue next-stage loads first (A cp.async + B LDG) ----
        float4 c0, c1, c2, c3;
        if (more) {
            stage_a_cpasync(sb, b, s + 1, qlr, tid);
            CP_COMMIT();
            const int kg = (s + 1) * KC;
            const float* cb = context + (size_t)(b * TLEN + t0) * DDIM + kg;
            const int row0 = tid >> 3, u = tid & 7;
            const int row1 = (tid + 256) >> 3;
            const int row2 = (tid + 512) >> 3;
            const int row3 = (tid + 768) >> 3;
            c0 = __ldg(reinterpret_cast<const float4*>(cb + (size_t)row0 * DDIM + u * 4));
            c1 = __ldg(reinterpret_cast<const float4*>(cb + (size_t)row1 * DDIM + u * 4));
            c2 = __ldg(reinterpret_cast<const float4*>(cb + (size_t)row2 * DDIM + u * 4));
            c3 = __ldg(reinterpret_cast<const float4*>(cb + (size_t)row3 * DDIM + u * 4));
        }

        // ---- MMAs for current stage (2 k16-steps) ----
        #pragma unroll
        for (int ks = 0; ks < 2; ++ks) {
            uint32_t bh[8], bl[8];
            #pragma unroll
            for (int p = 0; p < 2; ++p) {
                const int tile  = p * 2 + (quad >> 1);
                const int khalf = quad & 1;
                const int rowt  = tbase + tile * 8 + r;
                const uint32_t off = SWZ128((uint32_t)(rowt * 128 + kbase + ks * 32 + khalf * 16));
                LDSM_X4(bh + p * 4, sb + B_HI + off);
                LDSM_X4(bl + p * 4, sb + B_LO + off);
            }
            #pragma unroll
            for (int mt = 0; mt < 4; ++mt) {
                if (jbase + mt * 16 < ql) {
                    const int rowa = jbase + mt * 16 + ((quad & 1) << 3) + r;
                    const uint32_t off = SWZ128((uint32_t)(rowa * 128 + kbase + ks * 32 + ((quad >> 1) << 4)));
                    uint32_t ah[4], al[4];
                    LDSM_X4(ah, sb + A_HI + off);
                    LDSM_X4(al, sb + A_LO + off);
                    #pragma unroll
                    for (int nt = 0; nt < 4; ++nt) {
                        mma16816(acc[mt][nt], ah, bh + nt * 2);
                        mma16816(acc[mt][nt], al, bh + nt * 2);
                        mma16816(acc[mt][nt], ah, bl + nt * 2);
                    }
                }
            }
        }

        // ---- convert + store next-stage B into the other half-row ----
        if (more) {
            const uint32_t nkb = ((s + 1) & 1) << 6;
            uint32_t h01, h23, l01, l23;
            const int rows[4] = { tid >> 3, (tid + 256) >> 3, (tid + 512) >> 3, (tid + 768) >> 3 };
            const int u = tid & 7;
            split4(c0, h01, h23, l01, l23);
            uint32_t off = SWZ128((uint32_t)(rows[0] * 128 + nkb + u * 8));
            *reinterpret_cast<uint2*>(smem + B_HI + off) = make_uint2(h01, h23);
            *reinterpret_cast<uint2*>(smem + B_LO + off) = make_uint2(l01, l23);
            split4(c1, h01, h23, l01, l23);
            off = SWZ128((uint32_t)(rows[1] * 128 + nkb + u * 8));
            *reinterpret_cast<uint2*>(smem + B_HI + off) = make_uint2(h01, h23);
            *reinterpret_cast<uint2*>(smem + B_LO + off) = make_uint2(l01, l23);
            split4(c2, h01, h23, l01, l23);
            off = SWZ128((uint32_t)(rows[2] * 128 + nkb + u * 8));
            *reinterpret_cast<uint2*>(smem + B_HI + off) = make_uint2(h01, h23);
            *reinterpret_cast<uint2*>(smem + B_LO + off) = make_uint2(l01, l23);
            split4(c3, h01, h23, l01, l23);
            off = SWZ128((uint32_t)(rows[3] * 128 + nkb + u * 8));
            *reinterpret_cast<uint2*>(smem + B_HI + off) = make_uint2(h01, h23);
            *reinterpret_cast<uint2*>(smem + B_LO + off) = make_uint2(l01, l23);
            CP_WAIT0();
        }
        __syncthreads();
    }

    // =================== fused softmax epilogue ===================
    float* red  = reinterpret_cast<float*>(smem);          // 512 floats
    float* mfin = red + 512;                               // 128 floats

    const int g   = lane >> 2;
    const int tig = lane & 3;
    const int tw  = wid >> 1;
    const float NEG = -3.4028235e38f;

    float mrow[8];
    #pragma unroll
    for (int mt = 0; mt < 4; ++mt) {
        #pragma unroll
        for (int h = 0; h < 2; ++h) {
            float mm = NEG;
            #pragma unroll
            for (int nt = 0; nt < 4; ++nt) {
                const int tg = t0 + tbase + nt * 8 + tig * 2;
                const float v0 = (tg     < cl) ? acc[mt][nt][h * 2 + 0] : NEG;
                const float v1 = (tg + 1 < cl) ? acc[mt][nt][h * 2 + 1] : NEG;
                mm = fmaxf(mm, fmaxf(v0, v1));
            }
            mrow[mt * 2 + h] = mm;
        }
    }
    #pragma unroll
    for (int i = 0; i < 8; ++i) {
        mrow[i] = fmaxf(mrow[i], __shfl_xor_sync(0xffffffffu, mrow[i], 1));
        mrow[i] = fmaxf(mrow[i], __shfl_xor_sync(0xffffffffu, mrow[i], 2));
    }
    if (tig == 0) {
        #pragma unroll
        for (int mt = 0; mt < 4; ++mt)
            #pragma unroll
            for (int h = 0; h < 2; ++h) {
                const int row = jbase + mt * 16 + h * 8 + g;
                red[tw * 128 + row] = mrow[mt * 2 + h];
            }
    }
    __syncthreads();
    if (tid < 128)
        mfin[tid] = fmaxf(fmaxf(red[tid], red[128 + tid]),
                          fmaxf(red[256 + tid], red[384 + tid]));
    __syncthreads();

    float srow[8];
    #pragma unroll
    for (int mt = 0; mt < 4; ++mt) {
        const bool live = (jbase + mt * 16 < ql);
        #pragma unroll
        for (int h = 0; h < 2; ++h) {
            const int row = jbase + mt * 16 + h * 8 + g;
            float s = 0.0f;
            if (live) {
                const float mref = mfin[row];
                __half* prow = g_p + ((size_t)(b * JLEN + row)) * TLEN;
                #pragma unroll
                for (int nt = 0; nt < 4; ++nt) {
                    const int tg = t0 + tbase + nt * 8 + tig * 2;
                    const float e0 = (tg     < cl) ? __expf(acc[mt][nt][h * 2 + 0] - mref) : 0.0f;
                    const float e1 = (tg + 1 < cl) ? __expf(acc[mt][nt][h * 2 + 1] - mref) : 0.0f;
                    s += e0 + e1;
                    *reinterpret_cast<__half2*>(prow + tg) = __floats2half2_rn(e0, e1);
                }
            }
            srow[mt * 2 + h] = s;
        }
    }
    #pragma unroll
    for (int i = 0; i < 8; ++i) {
        srow[i] += __shfl_xor_sync(0xffffffffu, srow[i], 1);
        srow[i] += __shfl_xor_sync(0xffffffffu, srow[i], 2);
    }
    __syncthreads();
    if (tig == 0) {
        #pragma unroll
        for (int mt = 0; mt < 4; ++mt)
            #pragma unroll
            for (int h = 0; h < 2; ++h) {
                const int row = jbase + mt * 16 + h * 8 + g;
                red[tw * 128 + row] = srow[mt * 2 + h];
            }
    }
    __syncthreads();
    if (tid < 128) {
        const float S = red[tid] + red[128 + tid] + red[256 + tid] + red[384 + tid];
        const int tile = t0 >> 7;
        g_m[((size_t)(b * JLEN) + tid) * NTILE + tile] = mfin[tid];
        g_s[((size_t)(b * JLEN) + tid) * NTILE + tile] = S;
    }
}

// ---------------------------------------------------------------------------
// Kernel 2: partial out over a j-chunk of 8 (factors computed in-block).
// g_part[b][jc][t] = sum_{j in chunk} p[j][t] * factor[j][tile(t)]
// factor[j][k] = exp(m[j][k]-M[j]) / sum_k' s[j][k']*exp(m[j][k']-M[j])
// ---------------------------------------------------------------------------
__global__ __launch_bounds__(256) void out_part_kernel(
    const int* __restrict__ qlen,
    const int* __restrict__ clen)
{
    const int b  = blockIdx.y;
    const int jc = blockIdx.x;
    const int ql = qlen[b];
    const int cl = clen[b];
    const int ntl = (cl + TT - 1) / TT;
    const int j0 = jc * JCW;
    const int t8 = threadIdx.x * 8;

    __shared__ float sf[JCW][NTILE];
    if (threadIdx.x < JCW * NTILE) {
        const int jj = threadIdx.x >> 4;
        const int k  = threadIdx.x & 15;
        const int j  = j0 + jj;
        const float NEG = -3.4028235e38f;
        float mv = NEG, sv = 0.0f;
        if (j < ql && k < ntl) {
            mv = g_m[((size_t)(b * JLEN + j)) * NTILE + k];
            sv = g_s[((size_t)(b * JLEN + j)) * NTILE + k];
        }
        float M = mv;
        #pragma unroll
        for (int o = 8; o > 0; o >>= 1)
            M = fmaxf(M, __shfl_xor_sync(0xffffffffu, M, o));
        const float e = __expf(mv - M);       // dead entries underflow to 0 (or S guard)
        float S = sv * e;
        #pragma unroll
        for (int o = 8; o > 0; o >>= 1)
            S += __shfl_xor_sync(0xffffffffu, S, o);
        sf[jj][k] = (S > 0.0f) ? e / S : 0.0f;
    }
    __syncthreads();

    float a[8];
    #pragma unroll
    for (int i = 0; i < 8; ++i) a[i] = 0.0f;

    if (j0 < ql && t8 < cl) {
        const int tile = t8 >> 7;
        const __half* base = g_p + ((size_t)b * JLEN) * TLEN + t8;
        // 8 unconditional independent loads (row clamped; dead rows get factor 0)
        #pragma unroll
        for (int jj = 0; jj < JCW; ++jj) {
            const int j = min(j0 + jj, ql - 1);
            const uint4 u = *reinterpret_cast<const uint4*>(base + (size_t)j * TLEN);
            const float dj = sf[jj][tile];
            const __half2* h = reinterpret_cast<const __half2*>(&u);
            #pragma unroll
            for (int q = 0; q < 4; ++q) {
                const float2 fv = __half22float2(h[q]);
                a[q * 2 + 0] += fv.x * dj;
                a[q * 2 + 1] += fv.y * dj;
            }
        }
    }

    float* part = g_part + ((size_t)(b * NJC + jc)) * TLEN + t8;
    *reinterpret_cast<float4*>(part)     = make_float4(a[0], a[1], a[2], a[3]);
    *reinterpret_cast<float4*>(part + 4) = make_float4(a[4], a[5], a[6], a[7]);
}

// ---------------------------------------------------------------------------
// Kernel 3: out[b][t] = sum_{jc} g_part[b][jc][t]
// ---------------------------------------------------------------------------
__global__ __launch_bounds__(256) void combine_kernel(float* __restrict__ out)
{
    const int idx = blockIdx.x * 256 + threadIdx.x;
    const int b   = idx >> 9;
    const int t4  = (idx & 511) * 4;

    const float* p = g_part + ((size_t)b * NJC) * TLEN + t4;
    float4 s = make_float4(0.f, 0.f, 0.f, 0.f);
    #pragma unroll
    for (int jc = 0; jc < NJC; ++jc) {
        const float4 v = *reinterpret_cast<const float4*>(p + (size_t)jc * TLEN);
        s.x += v.x; s.y += v.y; s.z += v.z; s.w += v.w;
    }
    *reinterpret_cast<float4*>(out + (size_t)b * TLEN + t4) = s;
}

// ---------------------------------------------------------------------------
extern "C" void kernel_launch(void* const* d_in, const int* in_sizes, int n_in,
                              void* d_out, int out_size)
{
    const float* question = (const float*)d_in[0];
    const float* context  = (const float*)d_in[1];
    const int*   qlen     = (const int*)d_in[2];
    const int*   clen     = (const int*)d_in[3];
    const float* weight   = (const float*)d_in[4];
    float* out = (float*)d_out;

    cudaFuncSetAttribute(gemm_kernel, cudaFuncAttributeMaxDynamicSharedMemorySize, SM_TOTAL);

    prep_kernel<<<BATCH * JLEN, 128>>>(question, weight);

    dim3 g1(TLEN / TT, BATCH);              // 16 x 64
    gemm_kernel<<<g1, 256, SM_TOTAL>>>(context, qlen, clen);

    dim3 g3(NJC, BATCH);                    // 16 x 64
    out_part_kernel<<<g3, 256>>>(qlen, clen);

    combine_kernel<<<BATCH * TLEN / 1024, 256>>>(out);        // 128 x 256
}